// round 1
// baseline (speedup 1.0000x reference)
#include <cuda_runtime.h>
#include <cuda_bf16.h>
#include <mma.h>

using namespace nvcuda;

#define VOCAB  32000
#define EMBED  512
#define HIDDEN 512
#define CTXD   2048
#define BB     32
#define SS     64
#define MTOT   (BB * SS)      // 2048
#define GATES  (4 * HIDDEN)   // 2048

// ---------------- scratch (device globals; no allocation allowed) ----------------
__device__ float g_xg[MTOT * GATES];    // 16 MB : xg = emb@W_x + b
__device__ float g_hs[MTOT * HIDDEN];   // 4 MB  : h at every step, row m = b*64 + t
__device__ float g_h0[BB * HIDDEN];
__device__ float g_c [BB * HIDDEN];

// ---------------- kernel 1: h0 = tanh(ctx@W_ih + b_ih), c0 = tanh(ctx@W_ic + b_ic) ----------------
__global__ __launch_bounds__(512) void init_kernel(
    const float* __restrict__ context,
    const float* __restrict__ W_ih, const float* __restrict__ b_ih,
    const float* __restrict__ W_ic, const float* __restrict__ b_ic)
{
    __shared__ float ctx[CTXD];
    const int b = blockIdx.x;
    const int which = blockIdx.y;
    const int j = threadIdx.x;
    for (int i = j; i < CTXD; i += 512) ctx[i] = context[b * CTXD + i];
    __syncthreads();
    const float* W  = which ? W_ic : W_ih;
    const float* bv = which ? b_ic : b_ih;
    float acc = 0.f;
#pragma unroll 8
    for (int k = 0; k < CTXD; k++)
        acc += ctx[k] * __ldg(&W[(long)k * HIDDEN + j]);
    const float v = tanhf(acc + bv[j]);
    if (which) g_c [b * HIDDEN + j] = v;
    else       g_h0[b * HIDDEN + j] = v;
}

// ---------------- kernel 2: xg[m][g] = emb_table[tok[m]] @ W_x + b  (fp32 SGEMM, gather fused) ----------------
__global__ __launch_bounds__(256) void xg_kernel(
    const int*   __restrict__ tokens,
    const float* __restrict__ emb,
    const float* __restrict__ Wx,
    const float* __restrict__ bias)
{
    __shared__ float As[2][8][128];   // transposed A tile
    __shared__ float Bs[2][8][128];
    const int tid = threadIdx.x;
    const int tx = tid & 15, ty = tid >> 4;
    const int m0 = blockIdx.y * 128, n0 = blockIdx.x * 128;

    const int ar = tid >> 1;            // 0..127
    const int ac = (tid & 1) * 4;       // 0 or 4
    const int tok = tokens[m0 + ar];
    const float* aptr = emb + (long)tok * EMBED + ac;
    const int br = tid >> 5;            // 0..7
    const int bc = (tid & 31) * 4;
    const float* bptr = Wx + (long)br * GATES + n0 + bc;

    float acc[8][8];
#pragma unroll
    for (int i = 0; i < 8; i++)
#pragma unroll
        for (int j = 0; j < 8; j++) acc[i][j] = 0.f;

    { // prologue: chunk 0
        float4 av = *(const float4*)aptr;
        As[0][ac + 0][ar] = av.x; As[0][ac + 1][ar] = av.y;
        As[0][ac + 2][ar] = av.z; As[0][ac + 3][ar] = av.w;
        *(float4*)&Bs[0][br][bc] = *(const float4*)bptr;
    }
    __syncthreads();

    int buf = 0;
    for (int kc = 0; kc < 64; kc++) {
        if (kc < 63) {
            const int k0 = (kc + 1) * 8;
            float4 av = *(const float4*)(aptr + k0);
            float4 bv = *(const float4*)(bptr + (long)k0 * GATES);
            As[buf ^ 1][ac + 0][ar] = av.x; As[buf ^ 1][ac + 1][ar] = av.y;
            As[buf ^ 1][ac + 2][ar] = av.z; As[buf ^ 1][ac + 3][ar] = av.w;
            *(float4*)&Bs[buf ^ 1][br][bc] = bv;
        }
#pragma unroll
        for (int kk = 0; kk < 8; kk++) {
            float rA[8], rB[8];
            *(float4*)&rA[0] = *(const float4*)&As[buf][kk][ty * 8];
            *(float4*)&rA[4] = *(const float4*)&As[buf][kk][ty * 8 + 4];
            *(float4*)&rB[0] = *(const float4*)&Bs[buf][kk][tx * 8];
            *(float4*)&rB[4] = *(const float4*)&Bs[buf][kk][tx * 8 + 4];
#pragma unroll
            for (int i = 0; i < 8; i++)
#pragma unroll
                for (int j = 0; j < 8; j++) acc[i][j] += rA[i] * rB[j];
        }
        __syncthreads();
        buf ^= 1;
    }

    float bb[8];
#pragma unroll
    for (int j = 0; j < 8; j++) bb[j] = bias[n0 + tx * 8 + j];
#pragma unroll
    for (int i = 0; i < 8; i++) {
        const int row = m0 + ty * 8 + i;
        float* op = g_xg + (long)row * GATES + n0 + tx * 8;
        float4 v0 = make_float4(acc[i][0] + bb[0], acc[i][1] + bb[1],
                                acc[i][2] + bb[2], acc[i][3] + bb[3]);
        float4 v1 = make_float4(acc[i][4] + bb[4], acc[i][5] + bb[5],
                                acc[i][6] + bb[6], acc[i][7] + bb[7]);
        *(float4*)(op)     = v0;
        *(float4*)(op + 4) = v1;
    }
}

// ---------------- kernel 3: one LSTM step ----------------
// 128 CTAs, each owns 4 hidden units (jbase..jbase+3) for all 32 batches.
// smem: full h_{t-1} [32][516] + W_h slice transposed [16][516].
#define HSM_LD 516
#define LSTM_SMEM ((32 * HSM_LD + 16 * HSM_LD) * 4)   // 99072 bytes

__global__ __launch_bounds__(256) void lstm_step_kernel(
    const float* __restrict__ Wh,
    const int*   __restrict__ tokens,
    int t)
{
    extern __shared__ float sm[];
    float* hsm = sm;                      // [32][HSM_LD]
    float* Wsm = sm + 32 * HSM_LD;        // [16][HSM_LD], Wsm[c][k], c = gate*4 + jl
    __shared__ float red[128 * 4];

    const int tid = threadIdx.x;
    const int jbase = blockIdx.x * 4;

    // load h_{t-1} (full 32x512)
    for (int i4 = tid; i4 < 32 * 128; i4 += 256) {
        const int b  = i4 >> 7;
        const int k4 = (i4 & 127) * 4;
        const float* src = (t == 0) ? (g_h0 + b * HIDDEN + k4)
                                    : (g_hs + ((long)((b << 6) + t - 1)) * HIDDEN + k4);
        *(float4*)&hsm[b * HSM_LD + k4] = *(const float4*)src;
    }
    // load W_h columns {g*512 + jbase + jl}, transposed
    for (int idx = tid; idx < 16 * 512; idx += 256) {
        const int c = idx & 15;
        const int k = idx >> 4;
        const int col = ((c >> 2) << 9) + jbase + (c & 3);
        Wsm[c * HSM_LD + k] = Wh[(long)k * GATES + col];
    }
    __syncthreads();

    const int kh = tid >> 7;       // k half: 0 or 1
    const int r  = tid & 127;
    const int b  = r & 31;
    const int jl = r >> 5;         // 0..3

    float ai = 0.f, af_ = 0.f, ag = 0.f, ao = 0.f;
    const float* hp = hsm + b * HSM_LD + kh * 256;
    const float* wi = Wsm + (0  + jl) * HSM_LD + kh * 256;
    const float* wf = Wsm + (4  + jl) * HSM_LD + kh * 256;
    const float* wg = Wsm + (8  + jl) * HSM_LD + kh * 256;
    const float* wo = Wsm + (12 + jl) * HSM_LD + kh * 256;

#pragma unroll 8
    for (int k = 0; k < 256; k += 4) {
        const float4 h4 = *(const float4*)(hp + k);
        float4 v;
        v = *(const float4*)(wi + k); ai  += h4.x * v.x + h4.y * v.y + h4.z * v.z + h4.w * v.w;
        v = *(const float4*)(wf + k); af_ += h4.x * v.x + h4.y * v.y + h4.z * v.z + h4.w * v.w;
        v = *(const float4*)(wg + k); ag  += h4.x * v.x + h4.y * v.y + h4.z * v.z + h4.w * v.w;
        v = *(const float4*)(wo + k); ao  += h4.x * v.x + h4.y * v.y + h4.z * v.z + h4.w * v.w;
    }

    if (kh == 1) {
        red[r * 4 + 0] = ai; red[r * 4 + 1] = af_;
        red[r * 4 + 2] = ag; red[r * 4 + 3] = ao;
    }
    __syncthreads();
    if (kh == 0) {
        ai  += red[r * 4 + 0]; af_ += red[r * 4 + 1];
        ag  += red[r * 4 + 2]; ao  += red[r * 4 + 3];
        const int j = jbase + jl;
        const int m = (b << 6) + t;
        const long xb = (long)m * GATES;
        const float zi = g_xg[xb +        j] + ai;
        const float zf = g_xg[xb +  512 + j] + af_;
        const float zg = g_xg[xb + 1024 + j] + ag;
        const float zo = g_xg[xb + 1536 + j] + ao;
        const float c_old = g_c[b * HIDDEN + j];
        const float si = 1.f / (1.f + expf(-zi));
        const float sf = 1.f / (1.f + expf(-zf));
        const float so = 1.f / (1.f + expf(-zo));
        const float cn = sf * c_old + si * tanhf(zg);
        const float hn = so * tanhf(cn);
        const bool msk = (tokens[m] != 0);
        const float ho = msk ? hn : hsm[b * HSM_LD + j];
        const float co = msk ? cn : c_old;
        g_c[b * HIDDEN + j] = co;
        g_hs[(long)m * HIDDEN + j] = ho;
    }
}

// ---------------- kernel 4: logits = hs @ W_out + b_out  (tf32 wmma) ----------------
// CTA tile 128x256, BK=8, 8 warps, each warp 64x64 (4x4 frags of 16x16).
__global__ __launch_bounds__(256) void logits_kernel(
    const float* __restrict__ Wout,
    const float* __restrict__ bout,
    float* __restrict__ out)
{
    __shared__ float As[2][128 * 12];   // A tile 128x8, ld 12
    __shared__ float Bs[2][8 * 264];    // B tile 8x256, ld 264

    const int tid  = threadIdx.x;
    const int wid  = tid >> 5;
    const int lane = tid & 31;
    const int wm = wid >> 2;            // 0..1
    const int wn = wid & 3;             // 0..3
    const int m0 = blockIdx.y * 128;
    const int n0 = blockIdx.x * 256;

    wmma::fragment<wmma::accumulator, 16, 16, 8, float> acc[4][4];
#pragma unroll
    for (int i = 0; i < 4; i++)
#pragma unroll
        for (int j = 0; j < 4; j++) wmma::fill_fragment(acc[i][j], 0.f);

    const int ar = tid >> 1;
    const int ac = (tid & 1) * 4;
    const float* aptr = g_hs + (long)(m0 + ar) * HIDDEN + ac;
    const int br0 = tid >> 6;           // 0..3 (second load is +4)
    const int bc0 = (tid & 63) * 4;
    const float* bbase = Wout + (long)n0;

    // prologue
    {
        *(float4*)&As[0][ar * 12 + ac] = *(const float4*)aptr;
        *(float4*)&Bs[0][br0 * 264 + bc0]       = *(const float4*)(bbase + (long)br0 * VOCAB + bc0);
        *(float4*)&Bs[0][(br0 + 4) * 264 + bc0] = *(const float4*)(bbase + (long)(br0 + 4) * VOCAB + bc0);
    }
    __syncthreads();

    int buf = 0;
    for (int kc = 0; kc < 64; kc++) {
        if (kc < 63) {
            const int k0 = (kc + 1) * 8;
            *(float4*)&As[buf ^ 1][ar * 12 + ac] = *(const float4*)(aptr + k0);
            *(float4*)&Bs[buf ^ 1][br0 * 264 + bc0] =
                *(const float4*)(bbase + (long)(k0 + br0) * VOCAB + bc0);
            *(float4*)&Bs[buf ^ 1][(br0 + 4) * 264 + bc0] =
                *(const float4*)(bbase + (long)(k0 + br0 + 4) * VOCAB + bc0);
        }
        wmma::fragment<wmma::matrix_a, 16, 16, 8, wmma::precision::tf32, wmma::row_major> af[4];
        wmma::fragment<wmma::matrix_b, 16, 16, 8, wmma::precision::tf32, wmma::row_major> bf[4];
#pragma unroll
        for (int i = 0; i < 4; i++) {
            wmma::load_matrix_sync(af[i], &As[buf][(wm * 64 + i * 16) * 12], 12);
#pragma unroll
            for (int e = 0; e < af[i].num_elements; e++)
                af[i].x[e] = wmma::__float_to_tf32(af[i].x[e]);
        }
#pragma unroll
        for (int j = 0; j < 4; j++) {
            wmma::load_matrix_sync(bf[j], &Bs[buf][wn * 64 + j * 16], 264);
#pragma unroll
            for (int e = 0; e < bf[j].num_elements; e++)
                bf[j].x[e] = wmma::__float_to_tf32(bf[j].x[e]);
        }
#pragma unroll
        for (int i = 0; i < 4; i++)
#pragma unroll
            for (int j = 0; j < 4; j++)
                wmma::mma_sync(acc[i][j], af[i], bf[j], acc[i][j]);
        __syncthreads();
        buf ^= 1;
    }
    __syncthreads();

    // epilogue: per-warp staging, add bias, coalesced writes
    float* stage = ((float*)As) + wid * 320;   // 16x20 per warp
#pragma unroll
    for (int i = 0; i < 4; i++) {
#pragma unroll
        for (int j = 0; j < 4; j++) {
            wmma::store_matrix_sync(stage, acc[i][j], 20, wmma::mem_row_major);
            __syncwarp();
#pragma unroll
            for (int p = 0; p < 8; p++) {
                const int e = p * 32 + lane;
                const int row = e >> 4, col = e & 15;
                const int gm = m0 + wm * 64 + i * 16 + row;
                const int gn = n0 + wn * 64 + j * 16 + col;
                out[(long)gm * VOCAB + gn] = stage[row * 20 + col] + __ldg(&bout[gn]);
            }
            __syncwarp();
        }
    }
}

// ---------------- launch ----------------
extern "C" void kernel_launch(void* const* d_in, const int* in_sizes, int n_in,
                              void* d_out, int out_size)
{
    const int*   tokens  = (const int*)  d_in[0];
    const float* context = (const float*)d_in[1];
    const float* emb     = (const float*)d_in[2];
    const float* W_ih    = (const float*)d_in[3];
    const float* b_ih    = (const float*)d_in[4];
    const float* W_ic    = (const float*)d_in[5];
    const float* b_ic    = (const float*)d_in[6];
    const float* W_x     = (const float*)d_in[7];
    const float* W_h     = (const float*)d_in[8];
    const float* b_g     = (const float*)d_in[9];
    const float* W_out   = (const float*)d_in[10];
    const float* b_out   = (const float*)d_in[11];
    float* out = (float*)d_out;

    cudaFuncSetAttribute(lstm_step_kernel,
                         cudaFuncAttributeMaxDynamicSharedMemorySize, LSTM_SMEM);

    init_kernel<<<dim3(32, 2), 512>>>(context, W_ih, b_ih, W_ic, b_ic);
    xg_kernel<<<dim3(16, 16), 256>>>(tokens, emb, W_x, b_g);
    for (int t = 0; t < SS; t++)
        lstm_step_kernel<<<128, 256, LSTM_SMEM>>>(W_h, tokens, t);
    logits_kernel<<<dim3(125, 16), 256>>>(W_out, b_out, out);
}

// round 2
// speedup vs baseline: 1.2229x; 1.2229x over previous
#include <cuda_runtime.h>
#include <cuda_bf16.h>
#include <mma.h>

using namespace nvcuda;

#define VOCAB  32000
#define EMBED  512
#define HIDDEN 512
#define CTXD   2048
#define BB     32
#define SS     64
#define MTOT   (BB * SS)      // 2048
#define GATES  (4 * HIDDEN)   // 2048
#define NCTA   128

// ---------------- scratch (device globals; no allocation allowed) ----------------
__device__ float g_xg[MTOT * GATES];        // 16 MB : xg = emb@W_x + b
__device__ float g_hs[MTOT * HIDDEN];       // 4 MB  : h per step, row m = b*64 + t (for logits)
__device__ float g_hT[SS * HIDDEN * BB];    // 4 MB  : h transposed [t][j][b] (for recurrence)
__device__ float g_h0T[HIDDEN * BB];        // [j][b]
__device__ float g_c [BB * HIDDEN];
__device__ unsigned g_bar[SS];              // per-step grid barrier counters (zeroed at graph end)

// ---------------- kernel 1: h0 = tanh(ctx@W_ih + b_ih), c0 = tanh(ctx@W_ic + b_ic) ----------------
__global__ __launch_bounds__(512) void init_kernel(
    const float* __restrict__ context,
    const float* __restrict__ W_ih, const float* __restrict__ b_ih,
    const float* __restrict__ W_ic, const float* __restrict__ b_ic)
{
    __shared__ float ctx[CTXD];
    const int b = blockIdx.x;
    const int which = blockIdx.y;
    const int j = threadIdx.x;
    for (int i = j; i < CTXD; i += 512) ctx[i] = context[b * CTXD + i];
    __syncthreads();
    const float* W  = which ? W_ic : W_ih;
    const float* bv = which ? b_ic : b_ih;
    float acc = 0.f;
#pragma unroll 8
    for (int k = 0; k < CTXD; k++)
        acc += ctx[k] * __ldg(&W[(long)k * HIDDEN + j]);
    const float v = tanhf(acc + bv[j]);
    if (which) g_c  [b * HIDDEN + j] = v;
    else       g_h0T[j * BB + b]     = v;
}

// ---------------- kernel 2: xg[m][g] = emb_table[tok[m]] @ W_x + b  (fp32 SGEMM, gather fused) ----------------
__global__ __launch_bounds__(256) void xg_kernel(
    const int*   __restrict__ tokens,
    const float* __restrict__ emb,
    const float* __restrict__ Wx,
    const float* __restrict__ bias)
{
    __shared__ float As[2][8][128];   // transposed A tile
    __shared__ float Bs[2][8][128];
    const int tid = threadIdx.x;
    const int tx = tid & 15, ty = tid >> 4;
    const int m0 = blockIdx.y * 128, n0 = blockIdx.x * 128;

    const int ar = tid >> 1;            // 0..127
    const int ac = (tid & 1) * 4;       // 0 or 4
    const int tok = tokens[m0 + ar];
    const float* aptr = emb + (long)tok * EMBED + ac;
    const int br = tid >> 5;            // 0..7
    const int bc = (tid & 31) * 4;
    const float* bptr = Wx + (long)br * GATES + n0 + bc;

    float acc[8][8];
#pragma unroll
    for (int i = 0; i < 8; i++)
#pragma unroll
        for (int j = 0; j < 8; j++) acc[i][j] = 0.f;

    { // prologue: chunk 0
        float4 av = *(const float4*)aptr;
        As[0][ac + 0][ar] = av.x; As[0][ac + 1][ar] = av.y;
        As[0][ac + 2][ar] = av.z; As[0][ac + 3][ar] = av.w;
        *(float4*)&Bs[0][br][bc] = *(const float4*)bptr;
    }
    __syncthreads();

    int buf = 0;
    for (int kc = 0; kc < 64; kc++) {
        if (kc < 63) {
            const int k0 = (kc + 1) * 8;
            float4 av = *(const float4*)(aptr + k0);
            float4 bv = *(const float4*)(bptr + (long)k0 * GATES);
            As[buf ^ 1][ac + 0][ar] = av.x; As[buf ^ 1][ac + 1][ar] = av.y;
            As[buf ^ 1][ac + 2][ar] = av.z; As[buf ^ 1][ac + 3][ar] = av.w;
            *(float4*)&Bs[buf ^ 1][br][bc] = bv;
        }
#pragma unroll
        for (int kk = 0; kk < 8; kk++) {
            float rA[8], rB[8];
            *(float4*)&rA[0] = *(const float4*)&As[buf][kk][ty * 8];
            *(float4*)&rA[4] = *(const float4*)&As[buf][kk][ty * 8 + 4];
            *(float4*)&rB[0] = *(const float4*)&Bs[buf][kk][tx * 8];
            *(float4*)&rB[4] = *(const float4*)&Bs[buf][kk][tx * 8 + 4];
#pragma unroll
            for (int i = 0; i < 8; i++)
#pragma unroll
                for (int j = 0; j < 8; j++) acc[i][j] += rA[i] * rB[j];
        }
        __syncthreads();
        buf ^= 1;
    }

    float bb[8];
#pragma unroll
    for (int j = 0; j < 8; j++) bb[j] = bias[n0 + tx * 8 + j];
#pragma unroll
    for (int i = 0; i < 8; i++) {
        const int row = m0 + ty * 8 + i;
        float* op = g_xg + (long)row * GATES + n0 + tx * 8;
        float4 v0 = make_float4(acc[i][0] + bb[0], acc[i][1] + bb[1],
                                acc[i][2] + bb[2], acc[i][3] + bb[3]);
        float4 v1 = make_float4(acc[i][4] + bb[4], acc[i][5] + bb[5],
                                acc[i][6] + bb[6], acc[i][7] + bb[7]);
        *(float4*)(op)     = v0;
        *(float4*)(op + 4) = v1;
    }
}

// ---------------- kernel 3: persistent LSTM (all 64 steps in one launch) ----------------
// 128 CTAs, each owns 4 hidden units (16 W_h columns resident in smem for the whole kernel).
// Per step: reload h_{t-1} (transposed, coalesced), outer-product GEMM, grid barrier.
// smem floats: hsm 512*32 | wsm 512*16 | red 16*512 | rsum 512 | csm 128 | tsm 2048 ints
#define HSMF   (512 * 32)
#define WSMF   (512 * 16)
#define REDF   (16 * 512)
#define LSTM_SMEM ((HSMF + WSMF + REDF + 512 + 128) * 4 + MTOT * 4)

__global__ __launch_bounds__(256) void lstm_persist_kernel(
    const float* __restrict__ Wh,
    const int*   __restrict__ tokens)
{
    extern __shared__ float sm[];
    float* hsm  = sm;                     // [k][b]  512 x 32
    float* wsm  = sm + HSMF;              // [k][c]  512 x 16, c = gate*4 + jl
    float* red  = wsm + WSMF;             // [ksp][o] 16 x 512, o = b*16 + c
    float* rsum = red + REDF;             // [512]
    float* csm  = rsum + 512;             // [128]  c-state, idx = jl*32 + b
    int*   tsm  = (int*)(csm + 128);      // [2048] tokens

    const int tid = threadIdx.x;
    const int jbase = blockIdx.x * 4;

    // one-time loads: W_h slice (transposed), c0, tokens
    for (int idx = tid; idx < WSMF; idx += 256) {
        const int k = idx >> 4, c = idx & 15;
        wsm[idx] = Wh[(size_t)k * GATES + ((c >> 2) << 9) + jbase + (c & 3)];
    }
    if (tid < 128) {
        const int b = tid & 31, jl = tid >> 5;
        csm[tid] = g_c[b * HIDDEN + jbase + jl];
    }
    for (int idx = tid; idx < MTOT; idx += 256) tsm[idx] = tokens[idx];

    // compute-thread decomposition: 4 batches x 8 cols x 32 k per thread
    const int bg  = tid & 7;          // batch group: b = bg*4 .. +3
    const int cgr = (tid >> 3) & 1;   // col group:   c = cgr*8 .. +7
    const int ksp = tid >> 4;         // k split:     k = ksp*32 .. +31

    for (int t = 0; t < SS; t++) {
        // ---- load h_{t-1} transposed [k][b], fully coalesced ----
        {
            const float4* hsrc = (const float4*)((t == 0) ? g_h0T
                                    : (g_hT + (size_t)(t - 1) * HIDDEN * BB));
            float4* hd = (float4*)hsm;
#pragma unroll
            for (int i = 0; i < 16; i++) hd[tid + 256 * i] = hsrc[tid + 256 * i];
        }
        __syncthreads();

        // ---- outer-product accumulate ----
        float acc[4][8];
#pragma unroll
        for (int bi = 0; bi < 4; bi++)
#pragma unroll
            for (int ci = 0; ci < 8; ci++) acc[bi][ci] = 0.f;

        const float* hp = hsm + ksp * 32 * 32 + bg * 4;
        const float* wp = wsm + ksp * 32 * 16 + cgr * 8;
#pragma unroll 8
        for (int kk = 0; kk < 32; kk++) {
            const float4 hv = *(const float4*)(hp + kk * 32);
            const float4 w0 = *(const float4*)(wp + kk * 16);
            const float4 w1 = *(const float4*)(wp + kk * 16 + 4);
            const float hb[4] = {hv.x, hv.y, hv.z, hv.w};
            const float wc[8] = {w0.x, w0.y, w0.z, w0.w, w1.x, w1.y, w1.z, w1.w};
#pragma unroll
            for (int bi = 0; bi < 4; bi++)
#pragma unroll
                for (int ci = 0; ci < 8; ci++)
                    acc[bi][ci] += hb[bi] * wc[ci];
        }

        // ---- write partials ----
        {
            float* rp = red + ksp * 512 + (bg * 4) * 16 + cgr * 8;
#pragma unroll
            for (int bi = 0; bi < 4; bi++) {
                *(float4*)(rp + bi * 16)     = make_float4(acc[bi][0], acc[bi][1], acc[bi][2], acc[bi][3]);
                *(float4*)(rp + bi * 16 + 4) = make_float4(acc[bi][4], acc[bi][5], acc[bi][6], acc[bi][7]);
            }
        }
        __syncthreads();

        // ---- reduce 16 k-splits ----
        {
            const int o = tid * 2;
            float sx = 0.f, sy = 0.f;
#pragma unroll
            for (int ks = 0; ks < 16; ks++) {
                const float2 v = *(const float2*)&red[ks * 512 + o];
                sx += v.x; sy += v.y;
            }
            rsum[o] = sx; rsum[o + 1] = sy;
        }
        __syncthreads();

        // ---- finalize: activations, mask, state update, h writeback ----
        if (tid < 128) {
            const int b  = tid & 31;
            const int jl = tid >> 5;
            const int j  = jbase + jl;
            const int m  = (b << 6) + t;
            const size_t xb = (size_t)m * GATES;
            const float zi = g_xg[xb +        j] + rsum[b * 16 +  0 + jl];
            const float zf = g_xg[xb +  512 + j] + rsum[b * 16 +  4 + jl];
            const float zg = g_xg[xb + 1024 + j] + rsum[b * 16 +  8 + jl];
            const float zo = g_xg[xb + 1536 + j] + rsum[b * 16 + 12 + jl];
            const float c_old = csm[tid];
            const float si = 1.f / (1.f + expf(-zi));
            const float sf = 1.f / (1.f + expf(-zf));
            const float so = 1.f / (1.f + expf(-zo));
            const float cn = sf * c_old + si * tanhf(zg);
            const float hn = so * tanhf(cn);
            const bool msk = (tsm[m] != 0);
            const float ho = msk ? hn : hsm[j * 32 + b];
            const float co = msk ? cn : c_old;
            csm[tid] = co;
            g_hs[(size_t)m * HIDDEN + j] = ho;
            g_hT[((size_t)t * HIDDEN + j) * BB + b] = ho;
        }

        // ---- grid barrier (not needed after the last step) ----
        if (t < SS - 1) {
            __threadfence();
            __syncthreads();
            if (tid == 0) {
                atomicAdd(&g_bar[t], 1u);
                while (((volatile unsigned*)g_bar)[t] < (unsigned)NCTA) { }
                __threadfence();
            }
            __syncthreads();
        }
    }
}

// reset barrier counters so the next graph replay starts clean
__global__ void bar_reset_kernel() {
    if (threadIdx.x < SS) g_bar[threadIdx.x] = 0;
}

// ---------------- kernel 4: logits = hs @ W_out + b_out  (tf32 wmma) ----------------
__global__ __launch_bounds__(256) void logits_kernel(
    const float* __restrict__ Wout,
    const float* __restrict__ bout,
    float* __restrict__ out)
{
    __shared__ float As[2][128 * 12];   // A tile 128x8, ld 12
    __shared__ float Bs[2][8 * 264];    // B tile 8x256, ld 264

    const int tid  = threadIdx.x;
    const int wid  = tid >> 5;
    const int lane = tid & 31;
    const int wm = wid >> 2;            // 0..1
    const int wn = wid & 3;             // 0..3
    const int m0 = blockIdx.y * 128;
    const int n0 = blockIdx.x * 256;

    wmma::fragment<wmma::accumulator, 16, 16, 8, float> acc[4][4];
#pragma unroll
    for (int i = 0; i < 4; i++)
#pragma unroll
        for (int j = 0; j < 4; j++) wmma::fill_fragment(acc[i][j], 0.f);

    const int ar = tid >> 1;
    const int ac = (tid & 1) * 4;
    const float* aptr = g_hs + (long)(m0 + ar) * HIDDEN + ac;
    const int br0 = tid >> 6;           // 0..3 (second load is +4)
    const int bc0 = (tid & 63) * 4;
    const float* bbase = Wout + (long)n0;

    // prologue
    {
        *(float4*)&As[0][ar * 12 + ac] = *(const float4*)aptr;
        *(float4*)&Bs[0][br0 * 264 + bc0]       = *(const float4*)(bbase + (long)br0 * VOCAB + bc0);
        *(float4*)&Bs[0][(br0 + 4) * 264 + bc0] = *(const float4*)(bbase + (long)(br0 + 4) * VOCAB + bc0);
    }
    __syncthreads();

    int buf = 0;
    for (int kc = 0; kc < 64; kc++) {
        if (kc < 63) {
            const int k0 = (kc + 1) * 8;
            *(float4*)&As[buf ^ 1][ar * 12 + ac] = *(const float4*)(aptr + k0);
            *(float4*)&Bs[buf ^ 1][br0 * 264 + bc0] =
                *(const float4*)(bbase + (long)(k0 + br0) * VOCAB + bc0);
            *(float4*)&Bs[buf ^ 1][(br0 + 4) * 264 + bc0] =
                *(const float4*)(bbase + (long)(k0 + br0 + 4) * VOCAB + bc0);
        }
        wmma::fragment<wmma::matrix_a, 16, 16, 8, wmma::precision::tf32, wmma::row_major> af[4];
        wmma::fragment<wmma::matrix_b, 16, 16, 8, wmma::precision::tf32, wmma::row_major> bf[4];
#pragma unroll
        for (int i = 0; i < 4; i++) {
            wmma::load_matrix_sync(af[i], &As[buf][(wm * 64 + i * 16) * 12], 12);
#pragma unroll
            for (int e = 0; e < af[i].num_elements; e++)
                af[i].x[e] = wmma::__float_to_tf32(af[i].x[e]);
        }
#pragma unroll
        for (int j = 0; j < 4; j++) {
            wmma::load_matrix_sync(bf[j], &Bs[buf][wn * 64 + j * 16], 264);
#pragma unroll
            for (int e = 0; e < bf[j].num_elements; e++)
                bf[j].x[e] = wmma::__float_to_tf32(bf[j].x[e]);
        }
#pragma unroll
        for (int i = 0; i < 4; i++)
#pragma unroll
            for (int j = 0; j < 4; j++)
                wmma::mma_sync(acc[i][j], af[i], bf[j], acc[i][j]);
        __syncthreads();
        buf ^= 1;
    }
    __syncthreads();

    // epilogue: per-warp staging, add bias, coalesced writes
    float* stage = ((float*)As) + wid * 320;   // 16x20 per warp
#pragma unroll
    for (int i = 0; i < 4; i++) {
#pragma unroll
        for (int j = 0; j < 4; j++) {
            wmma::store_matrix_sync(stage, acc[i][j], 20, wmma::mem_row_major);
            __syncwarp();
#pragma unroll
            for (int p = 0; p < 8; p++) {
                const int e = p * 32 + lane;
                const int row = e >> 4, col = e & 15;
                const int gm = m0 + wm * 64 + i * 16 + row;
                const int gn = n0 + wn * 64 + j * 16 + col;
                out[(long)gm * VOCAB + gn] = stage[row * 20 + col] + __ldg(&bout[gn]);
            }
            __syncwarp();
        }
    }
}

// ---------------- launch ----------------
extern "C" void kernel_launch(void* const* d_in, const int* in_sizes, int n_in,
                              void* d_out, int out_size)
{
    const int*   tokens  = (const int*)  d_in[0];
    const float* context = (const float*)d_in[1];
    const float* emb     = (const float*)d_in[2];
    const float* W_ih    = (const float*)d_in[3];
    const float* b_ih    = (const float*)d_in[4];
    const float* W_ic    = (const float*)d_in[5];
    const float* b_ic    = (const float*)d_in[6];
    const float* W_x     = (const float*)d_in[7];
    const float* W_h     = (const float*)d_in[8];
    const float* b_g     = (const float*)d_in[9];
    const float* W_out   = (const float*)d_in[10];
    const float* b_out   = (const float*)d_in[11];
    float* out = (float*)d_out;

    cudaFuncSetAttribute(lstm_persist_kernel,
                         cudaFuncAttributeMaxDynamicSharedMemorySize, LSTM_SMEM);

    init_kernel<<<dim3(32, 2), 512>>>(context, W_ih, b_ih, W_ic, b_ic);
    xg_kernel<<<dim3(16, 16), 256>>>(tokens, emb, W_x, b_g);
    lstm_persist_kernel<<<NCTA, 256, LSTM_SMEM>>>(W_h, tokens);
    bar_reset_kernel<<<1, 64>>>();
    logits_kernel<<<dim3(125, 16), 256>>>(W_out, b_out, out);
}

// round 4
// speedup vs baseline: 1.2827x; 1.0489x over previous
#include <cuda_runtime.h>
#include <cuda_bf16.h>
#include <mma.h>

using namespace nvcuda;

#define VOCAB  32000
#define EMBED  512
#define HIDDEN 512
#define CTXD   2048
#define BB     32
#define SS     64
#define MTOT   (BB * SS)      // 2048
#define GATES  (4 * HIDDEN)   // 2048
#define NCTA   128

// ---------------- scratch (device globals; no allocation allowed) ----------------
__device__ float g_xg[MTOT * GATES];        // 16 MB : xg = emb@W_x + b
__device__ float g_hs[MTOT * HIDDEN];       // 4 MB  : h per step, row m = b*64 + t
__device__ float g_h0[BB * HIDDEN];         // [b][j], tf32-rounded
__device__ float g_c [BB * HIDDEN];
__device__ unsigned g_bar[SS];              // per-step grid barrier counters

// ---------------- kernel 1: h0 = tanh(ctx@W_ih), c0 = tanh(ctx@W_ic) ----------------
__global__ __launch_bounds__(512) void init_kernel(
    const float* __restrict__ context,
    const float* __restrict__ W_ih, const float* __restrict__ b_ih,
    const float* __restrict__ W_ic, const float* __restrict__ b_ic)
{
    __shared__ float ctx[CTXD];
    const int b = blockIdx.x;
    const int which = blockIdx.y;
    const int j = threadIdx.x;
    for (int i = j; i < CTXD; i += 512) ctx[i] = context[b * CTXD + i];
    __syncthreads();
    const float* W  = which ? W_ic : W_ih;
    const float* bv = which ? b_ic : b_ih;
    float acc = 0.f;
#pragma unroll 8
    for (int k = 0; k < CTXD; k++)
        acc += ctx[k] * __ldg(&W[(long)k * HIDDEN + j]);
    const float v = tanhf(acc + bv[j]);
    if (which) g_c [b * HIDDEN + j] = v;
    else       g_h0[b * HIDDEN + j] = wmma::__float_to_tf32(v);
}

// ---------------- kernel 2: xg = gather(emb)@W_x + b  (fp32 SGEMM) ----------------
__global__ __launch_bounds__(256) void xg_kernel(
    const int*   __restrict__ tokens,
    const float* __restrict__ emb,
    const float* __restrict__ Wx,
    const float* __restrict__ bias)
{
    __shared__ float As[2][8][128];
    __shared__ float Bs[2][8][128];
    const int tid = threadIdx.x;
    const int tx = tid & 15, ty = tid >> 4;
    const int m0 = blockIdx.y * 128, n0 = blockIdx.x * 128;

    const int ar = tid >> 1;
    const int ac = (tid & 1) * 4;
    const int tok = tokens[m0 + ar];
    const float* aptr = emb + (long)tok * EMBED + ac;
    const int br = tid >> 5;
    const int bc = (tid & 31) * 4;
    const float* bptr = Wx + (long)br * GATES + n0 + bc;

    float acc[8][8];
#pragma unroll
    for (int i = 0; i < 8; i++)
#pragma unroll
        for (int j = 0; j < 8; j++) acc[i][j] = 0.f;

    {
        float4 av = *(const float4*)aptr;
        As[0][ac + 0][ar] = av.x; As[0][ac + 1][ar] = av.y;
        As[0][ac + 2][ar] = av.z; As[0][ac + 3][ar] = av.w;
        *(float4*)&Bs[0][br][bc] = *(const float4*)bptr;
    }
    __syncthreads();

    int buf = 0;
    for (int kc = 0; kc < 64; kc++) {
        if (kc < 63) {
            const int k0 = (kc + 1) * 8;
            float4 av = *(const float4*)(aptr + k0);
            float4 bv = *(const float4*)(bptr + (long)k0 * GATES);
            As[buf ^ 1][ac + 0][ar] = av.x; As[buf ^ 1][ac + 1][ar] = av.y;
            As[buf ^ 1][ac + 2][ar] = av.z; As[buf ^ 1][ac + 3][ar] = av.w;
            *(float4*)&Bs[buf ^ 1][br][bc] = bv;
        }
#pragma unroll
        for (int kk = 0; kk < 8; kk++) {
            float rA[8], rB[8];
            *(float4*)&rA[0] = *(const float4*)&As[buf][kk][ty * 8];
            *(float4*)&rA[4] = *(const float4*)&As[buf][kk][ty * 8 + 4];
            *(float4*)&rB[0] = *(const float4*)&Bs[buf][kk][tx * 8];
            *(float4*)&rB[4] = *(const float4*)&Bs[buf][kk][tx * 8 + 4];
#pragma unroll
            for (int i = 0; i < 8; i++)
#pragma unroll
                for (int j = 0; j < 8; j++) acc[i][j] += rA[i] * rB[j];
        }
        __syncthreads();
        buf ^= 1;
    }

    float bb[8];
#pragma unroll
    for (int j = 0; j < 8; j++) bb[j] = bias[n0 + tx * 8 + j];
#pragma unroll
    for (int i = 0; i < 8; i++) {
        const int row = m0 + ty * 8 + i;
        float* op = g_xg + (long)row * GATES + n0 + tx * 8;
        float4 v0 = make_float4(acc[i][0] + bb[0], acc[i][1] + bb[1],
                                acc[i][2] + bb[2], acc[i][3] + bb[3]);
        float4 v1 = make_float4(acc[i][4] + bb[4], acc[i][5] + bb[5],
                                acc[i][6] + bb[6], acc[i][7] + bb[7]);
        *(float4*)(op)     = v0;
        *(float4*)(op + 4) = v1;
    }
}

// ---------------- kernel 3: persistent LSTM, tf32 wmma recurrence ----------------
// 128 CTAs x 256 threads (8 warps). CTA owns 4 hidden units = 16 gate columns.
// W_h slice lives in register B-fragments for the whole kernel.
// Per step: prefetch xg, load h (32x512, tf32-rounded) to smem, wmma k-split,
// smem reduce, activations, grid barrier.
#define HLD    520                       // 512 + 8 pad
#define HSMF   (32 * HLD)                // 16640
#define WSMF   (512 * 16)                // 8192 (only used during preload)
#define REDF   (8 * 512)                 // 4096
#define LSTM_SMEM ((HSMF + WSMF + REDF + 512 + 128) * 4 + MTOT * 4)

__global__ __launch_bounds__(256) void lstm_persist_kernel(
    const float* __restrict__ Wh,
    const int*   __restrict__ tokens)
{
    extern __shared__ float sm[];
    float* hsm  = sm;                     // [b][k]  32 x HLD
    float* wsm  = sm + HSMF;              // [k][c]  512 x 16 (preload staging)
    float* red  = wsm + WSMF;             // [w][b*16+c]  8 x 512
    float* rsum = red + REDF;             // [512]
    float* csm  = rsum + 512;             // [128]  c-state, idx = jl*32+b
    int*   tsm  = (int*)(csm + 128);      // [2048] tokens

    const int tid  = threadIdx.x;
    const int wid  = tid >> 5;
    const int jbase = blockIdx.x * 4;

    // ---- one-time: gather W_h columns into smem, tf32-round ----
    for (int idx = tid; idx < WSMF; idx += 256) {
        const int k = idx >> 4, c = idx & 15;
        wsm[idx] = wmma::__float_to_tf32(
            Wh[(size_t)k * GATES + ((c >> 2) << 9) + jbase + (c & 3)]);
    }
    if (tid < 128) {
        const int b = tid & 31, jl = tid >> 5;
        csm[tid] = g_c[b * HIDDEN + jbase + jl];
    }
    for (int idx = tid; idx < MTOT; idx += 256) tsm[idx] = tokens[idx];
    __syncthreads();

    // ---- preload B fragments: warp wid owns k in [wid*64, wid*64+64) ----
    wmma::fragment<wmma::matrix_b, 16, 16, 8, wmma::precision::tf32, wmma::row_major> bk[8];
#pragma unroll
    for (int ks = 0; ks < 8; ks++)
        wmma::load_matrix_sync(bk[ks], &wsm[(wid * 64 + ks * 8) * 16], 16);
    __syncthreads();

    for (int t = 0; t < SS; t++) {
        // ---- prefetch xg for this step (overlaps with h load) ----
        float x0 = 0.f, x1 = 0.f, x2 = 0.f, x3 = 0.f;
        int b_f = 0, jl_f = 0, m_f = 0;
        if (tid < 128) {
            b_f = tid & 31; jl_f = tid >> 5;
            m_f = (b_f << 6) + t;
            const size_t xb = (size_t)m_f * GATES + jbase + jl_f;
            x0 = g_xg[xb];
            x1 = g_xg[xb + 512];
            x2 = g_xg[xb + 1024];
            x3 = g_xg[xb + 1536];
        }

        // ---- load h_{t-1} into smem [b][k] (coalesced 2KB rows) ----
        {
#pragma unroll
            for (int i = 0; i < 16; i++) {
                const int idx = tid + 256 * i;        // 0..4095
                const int b  = idx >> 7;
                const int k4 = (idx & 127) << 2;
                const float4 v = (t == 0)
                    ? *(const float4*)&g_h0[b * HIDDEN + k4]
                    : *(const float4*)&g_hs[(size_t)((b << 6) + t - 1) * HIDDEN + k4];
                *(float4*)&hsm[b * HLD + k4] = v;
            }
        }
        __syncthreads();

        // ---- wmma: z-partial (32x16) over this warp's 64-wide k slice ----
        wmma::fragment<wmma::accumulator, 16, 16, 8, float> acc0, acc1;
        wmma::fill_fragment(acc0, 0.f);
        wmma::fill_fragment(acc1, 0.f);
#pragma unroll
        for (int ks = 0; ks < 8; ks++) {
            const int k0 = wid * 64 + ks * 8;
            wmma::fragment<wmma::matrix_a, 16, 16, 8, wmma::precision::tf32, wmma::row_major> a0, a1;
            wmma::load_matrix_sync(a0, &hsm[k0], HLD);            // rows 0..15  (already tf32 bits)
            wmma::load_matrix_sync(a1, &hsm[16 * HLD + k0], HLD); // rows 16..31
            wmma::mma_sync(acc0, a0, bk[ks], acc0);
            wmma::mma_sync(acc1, a1, bk[ks], acc1);
        }
        wmma::store_matrix_sync(&red[wid * 512],       acc0, 16, wmma::mem_row_major);
        wmma::store_matrix_sync(&red[wid * 512 + 256], acc1, 16, wmma::mem_row_major);
        __syncthreads();

        // ---- reduce 8 warp partials: rsum[b*16+c] ----
        {
            float s0 = 0.f, s1 = 0.f;
            const int o = tid;
#pragma unroll
            for (int w = 0; w < 8; w++) {
                s0 += red[w * 512 + o];
                s1 += red[w * 512 + o + 256];
            }
            rsum[o] = s0; rsum[o + 256] = s1;
        }
        __syncthreads();

        // ---- finalize: activations, mask, state update, h writeback ----
        if (tid < 128) {
            const int b = b_f, jl = jl_f, m = m_f;
            const int j = jbase + jl;
            const float zi = x0 + rsum[b * 16 +  0 + jl];
            const float zf = x1 + rsum[b * 16 +  4 + jl];
            const float zg = x2 + rsum[b * 16 +  8 + jl];
            const float zo = x3 + rsum[b * 16 + 12 + jl];
            const float c_old = csm[tid];
            const float si = 1.f / (1.f + expf(-zi));
            const float sf = 1.f / (1.f + expf(-zf));
            const float so = 1.f / (1.f + expf(-zo));
            const float cn = sf * c_old + si * tanhf(zg);
            const float hn = so * tanhf(cn);
            const bool msk = (tsm[m] != 0);
            const float ho = msk ? wmma::__float_to_tf32(hn) : hsm[b * HLD + j];
            const float co = msk ? cn : c_old;
            csm[tid] = co;
            g_hs[(size_t)m * HIDDEN + j] = ho;
        }

        // ---- grid barrier (sleep-wait spin; 128 co-resident CTAs) ----
        if (t < SS - 1) {
            __threadfence();
            __syncthreads();
            if (tid == 0) {
                atomicAdd(&g_bar[t], 1u);
                while (((volatile unsigned*)g_bar)[t] < (unsigned)NCTA)
                    __nanosleep(64);
                __threadfence();
            }
            __syncthreads();
        }
    }
}

// reset barrier counters (runs BEFORE lstm each replay; globals start zeroed)
__global__ void bar_reset_kernel() {
    if (threadIdx.x < SS) g_bar[threadIdx.x] = 0;
}

// ---------------- kernel 4: logits = hs @ W_out + b_out  (tf32 wmma) ----------------
__global__ __launch_bounds__(256) void logits_kernel(
    const float* __restrict__ Wout,
    const float* __restrict__ bout,
    float* __restrict__ out)
{
    __shared__ float As[2][128 * 12];
    __shared__ float Bs[2][8 * 264];

    const int tid  = threadIdx.x;
    const int wid  = tid >> 5;
    const int lane = tid & 31;
    const int wm = wid >> 2;
    const int wn = wid & 3;
    const int m0 = blockIdx.y * 128;
    const int n0 = blockIdx.x * 256;

    wmma::fragment<wmma::accumulator, 16, 16, 8, float> acc[4][4];
#pragma unroll
    for (int i = 0; i < 4; i++)
#pragma unroll
        for (int j = 0; j < 4; j++) wmma::fill_fragment(acc[i][j], 0.f);

    const int ar = tid >> 1;
    const int ac = (tid & 1) * 4;
    const float* aptr = g_hs + (long)(m0 + ar) * HIDDEN + ac;
    const int br0 = tid >> 6;
    const int bc0 = (tid & 63) * 4;
    const float* bbase = Wout + (long)n0;

    {
        *(float4*)&As[0][ar * 12 + ac] = *(const float4*)aptr;
        *(float4*)&Bs[0][br0 * 264 + bc0]       = *(const float4*)(bbase + (long)br0 * VOCAB + bc0);
        *(float4*)&Bs[0][(br0 + 4) * 264 + bc0] = *(const float4*)(bbase + (long)(br0 + 4) * VOCAB + bc0);
    }
    __syncthreads();

    int buf = 0;
    for (int kc = 0; kc < 64; kc++) {
        if (kc < 63) {
            const int k0 = (kc + 1) * 8;
            *(float4*)&As[buf ^ 1][ar * 12 + ac] = *(const float4*)(aptr + k0);
            *(float4*)&Bs[buf ^ 1][br0 * 264 + bc0] =
                *(const float4*)(bbase + (long)(k0 + br0) * VOCAB + bc0);
            *(float4*)&Bs[buf ^ 1][(br0 + 4) * 264 + bc0] =
                *(const float4*)(bbase + (long)(k0 + br0 + 4) * VOCAB + bc0);
        }
        wmma::fragment<wmma::matrix_a, 16, 16, 8, wmma::precision::tf32, wmma::row_major> af[4];
        wmma::fragment<wmma::matrix_b, 16, 16, 8, wmma::precision::tf32, wmma::row_major> bf[4];
#pragma unroll
        for (int i = 0; i < 4; i++) {
            wmma::load_matrix_sync(af[i], &As[buf][(wm * 64 + i * 16) * 12], 12);
#pragma unroll
            for (int e = 0; e < af[i].num_elements; e++)
                af[i].x[e] = wmma::__float_to_tf32(af[i].x[e]);
        }
#pragma unroll
        for (int j = 0; j < 4; j++) {
            wmma::load_matrix_sync(bf[j], &Bs[buf][wn * 64 + j * 16], 264);
#pragma unroll
            for (int e = 0; e < bf[j].num_elements; e++)
                bf[j].x[e] = wmma::__float_to_tf32(bf[j].x[e]);
        }
#pragma unroll
        for (int i = 0; i < 4; i++)
#pragma unroll
            for (int j = 0; j < 4; j++)
                wmma::mma_sync(acc[i][j], af[i], bf[j], acc[i][j]);
        __syncthreads();
        buf ^= 1;
    }
    __syncthreads();

    float* stage = ((float*)As) + wid * 320;
#pragma unroll
    for (int i = 0; i < 4; i++) {
#pragma unroll
        for (int j = 0; j < 4; j++) {
            wmma::store_matrix_sync(stage, acc[i][j], 20, wmma::mem_row_major);
            __syncwarp();
#pragma unroll
            for (int p = 0; p < 8; p++) {
                const int e = p * 32 + lane;
                const int row = e >> 4, col = e & 15;
                const int gm = m0 + wm * 64 + i * 16 + row;
                const int gn = n0 + wn * 64 + j * 16 + col;
                out[(long)gm * VOCAB + gn] = stage[row * 20 + col] + __ldg(&bout[gn]);
            }
            __syncwarp();
        }
    }
}

// ---------------- launch ----------------
extern "C" void kernel_launch(void* const* d_in, const int* in_sizes, int n_in,
                              void* d_out, int out_size)
{
    const int*   tokens  = (const int*)  d_in[0];
    const float* context = (const float*)d_in[1];
    const float* emb     = (const float*)d_in[2];
    const float* W_ih    = (const float*)d_in[3];
    const float* b_ih    = (const float*)d_in[4];
    const float* W_ic    = (const float*)d_in[5];
    const float* b_ic    = (const float*)d_in[6];
    const float* W_x     = (const float*)d_in[7];
    const float* W_h     = (const float*)d_in[8];
    const float* b_g     = (const float*)d_in[9];
    const float* W_out   = (const float*)d_in[10];
    const float* b_out   = (const float*)d_in[11];
    float* out = (float*)d_out;

    cudaFuncSetAttribute(lstm_persist_kernel,
                         cudaFuncAttributeMaxDynamicSharedMemorySize, LSTM_SMEM);

    init_kernel<<<dim3(32, 2), 512>>>(context, W_ih, b_ih, W_ic, b_ic);
    xg_kernel<<<dim3(16, 16), 256>>>(tokens, emb, W_x, b_g);
    bar_reset_kernel<<<1, 64>>>();                       // reset BEFORE use; also aligns ncu -s 5
    lstm_persist_kernel<<<NCTA, 256, LSTM_SMEM>>>(W_h, tokens);
    logits_kernel<<<dim3(125, 16), 256>>>(W_out, b_out, out);
}

// round 6
// speedup vs baseline: 1.2958x; 1.0102x over previous
#include <cuda_runtime.h>
#include <cuda_bf16.h>
#include <mma.h>

using namespace nvcuda;

#define VOCAB  32000
#define EMBED  512
#define HIDDEN 512
#define CTXD   2048
#define BB     32
#define SS     64
#define MTOT   (BB * SS)      // 2048
#define GATES  (4 * HIDDEN)   // 2048
#define NCTA   128

// ---------------- scratch (device globals; no allocation allowed) ----------------
__device__ float g_xg[MTOT * GATES];        // 16 MB : xg = emb@W_x + b
__device__ float g_hs[MTOT * HIDDEN];       // 4 MB  : h per step (tf32 values in fp32)
__device__ float g_h0[BB * HIDDEN];         // [b][j], tf32-rounded
__device__ float g_c [BB * HIDDEN];
__device__ unsigned g_bar[SS];              // per-step grid barrier counters

// ---------------- kernel 1: [h0|c0] = tanh(ctx @ [W_ih|W_ic] + [b_ih|b_ic])  (tf32 wmma) ----------------
// M=32, N=1024 (cols 0-511 -> h0 via W_ih, 512-1023 -> c0 via W_ic), K=2048.
// 16 CTAs x 128 threads (4 warps); CTA tile 32x64; warp tile 32x16.
__global__ __launch_bounds__(128) void init_gemm_kernel(
    const float* __restrict__ context,
    const float* __restrict__ W_ih, const float* __restrict__ b_ih,
    const float* __restrict__ W_ic, const float* __restrict__ b_ic)
{
    __shared__ float Asm[32 * 68];   // [m][k] ld 68
    __shared__ float Bsm[64 * 68];   // [k][n] ld 68

    const int tid = threadIdx.x;
    const int wid = tid >> 5;
    const int lane = tid & 31;
    const int n0 = blockIdx.x * 64;          // 0..960
    const bool which = (n0 >= 512);
    const int ncol = n0 & 511;
    const float* W  = which ? W_ic : W_ih;
    const float* bv = which ? b_ic : b_ih;

    wmma::fragment<wmma::accumulator, 16, 16, 8, float> acc0, acc1;
    wmma::fill_fragment(acc0, 0.f);
    wmma::fill_fragment(acc1, 0.f);

    for (int kc = 0; kc < 32; kc++) {
        const int k0 = kc * 64;
        // A: context[32][k0..k0+63]; thread: row=tid>>2, 4 float4 at cols (tid&3)*16
        {
            const int row = tid >> 2;
            const int cb  = (tid & 3) * 16;
            const float* src = context + (size_t)row * CTXD + k0 + cb;
            float* dst = Asm + row * 68 + cb;
#pragma unroll
            for (int i = 0; i < 4; i++) {
                float4 v = *(const float4*)(src + i * 4);
                dst[i * 4 + 0] = wmma::__float_to_tf32(v.x);
                dst[i * 4 + 1] = wmma::__float_to_tf32(v.y);
                dst[i * 4 + 2] = wmma::__float_to_tf32(v.z);
                dst[i * 4 + 3] = wmma::__float_to_tf32(v.w);
            }
        }
        // B: W[k0+r][ncol..ncol+63]; thread: r=tid>>1, 8 float4 at cols (tid&1)*4 + i*8
        {
            const int r  = tid >> 1;
            const int c0 = (tid & 1) * 4;
            const float* src = W + (size_t)(k0 + r) * HIDDEN + ncol + c0;
            float* dst = Bsm + r * 68 + c0;
#pragma unroll
            for (int i = 0; i < 8; i++) {
                float4 v = *(const float4*)(src + i * 8);
                dst[i * 8 + 0] = wmma::__float_to_tf32(v.x);
                dst[i * 8 + 1] = wmma::__float_to_tf32(v.y);
                dst[i * 8 + 2] = wmma::__float_to_tf32(v.z);
                dst[i * 8 + 3] = wmma::__float_to_tf32(v.w);
            }
        }
        __syncthreads();
#pragma unroll
        for (int ks = 0; ks < 8; ks++) {
            wmma::fragment<wmma::matrix_a, 16, 16, 8, wmma::precision::tf32, wmma::row_major> a0, a1;
            wmma::fragment<wmma::matrix_b, 16, 16, 8, wmma::precision::tf32, wmma::row_major> bf;
            wmma::load_matrix_sync(a0, &Asm[ks * 8], 68);
            wmma::load_matrix_sync(a1, &Asm[16 * 68 + ks * 8], 68);
            wmma::load_matrix_sync(bf, &Bsm[(ks * 8) * 68 + wid * 16], 68);
            wmma::mma_sync(acc0, a0, bf, acc0);
            wmma::mma_sync(acc1, a1, bf, acc1);
        }
        __syncthreads();
    }

    // epilogue: tanh(+bias), write h0 (tf32-rounded) or c0 (fp32)
    float* stage = Asm + wid * 640;          // 32x20 per warp
    wmma::store_matrix_sync(stage, acc0, 20, wmma::mem_row_major);
    wmma::store_matrix_sync(stage + 16 * 20, acc1, 20, wmma::mem_row_major);
    __syncwarp();
#pragma unroll
    for (int p = 0; p < 16; p++) {
        const int e = p * 32 + lane;         // 0..511
        const int r = e >> 4, c = e & 15;    // b = r, local col c
        const int j = ncol + wid * 16 + c;
        const float v = tanhf(stage[r * 20 + c] + bv[j]);
        if (which) g_c [r * HIDDEN + j] = v;
        else       g_h0[r * HIDDEN + j] = wmma::__float_to_tf32(v);
    }
}

// ---------------- kernel 2: xg = gather(emb)@W_x + b  (tf32 wmma, 128x128, BK=16) ----------------
__global__ __launch_bounds__(256) void xg_kernel(
    const int*   __restrict__ tokens,
    const float* __restrict__ emb,
    const float* __restrict__ Wx,
    const float* __restrict__ bias)
{
    __shared__ float As[2][128 * 20];   // [m][k] ld 20
    __shared__ float Bs[2][16 * 132];   // [k][n] ld 132

    const int tid = threadIdx.x;
    const int wid = tid >> 5;
    const int lane = tid & 31;
    const int wm = wid >> 2;            // 0..1 : 64-row half
    const int wn = wid & 3;             // 0..3 : 32-col quarter
    const int m0 = blockIdx.y * 128, n0 = blockIdx.x * 128;

    // A gather setup: row = tid>>1, two float4 at cols (tid&1)*8 {+0,+4}
    const int arow = tid >> 1;
    const int acol = (tid & 1) * 8;
    const int tok  = tokens[m0 + arow];
    const float* aptr = emb + (size_t)tok * EMBED + acol;
    // B: row = tid>>4 (16 rows), two float4 at cols (tid&15)*4 + i*64
    const int brow = tid >> 4;
    const int bcol = (tid & 15) * 4;
    const float* bptr = Wx + (size_t)brow * GATES + n0 + bcol;

    wmma::fragment<wmma::accumulator, 16, 16, 8, float> acc[4][2];
#pragma unroll
    for (int i = 0; i < 4; i++)
#pragma unroll
        for (int j = 0; j < 2; j++) wmma::fill_fragment(acc[i][j], 0.f);

    auto load_chunk = [&](int buf, int k0) {
        {
            float* dst = &As[buf][arow * 20 + acol];
            float4 v0 = *(const float4*)(aptr + k0);
            float4 v1 = *(const float4*)(aptr + k0 + 4);
            dst[0] = wmma::__float_to_tf32(v0.x); dst[1] = wmma::__float_to_tf32(v0.y);
            dst[2] = wmma::__float_to_tf32(v0.z); dst[3] = wmma::__float_to_tf32(v0.w);
            dst[4] = wmma::__float_to_tf32(v1.x); dst[5] = wmma::__float_to_tf32(v1.y);
            dst[6] = wmma::__float_to_tf32(v1.z); dst[7] = wmma::__float_to_tf32(v1.w);
        }
        {
            float* dst = &Bs[buf][brow * 132 + bcol];
#pragma unroll
            for (int i = 0; i < 2; i++) {
                float4 v = *(const float4*)(bptr + (size_t)k0 * GATES + i * 64);
                dst[i * 64 + 0] = wmma::__float_to_tf32(v.x);
                dst[i * 64 + 1] = wmma::__float_to_tf32(v.y);
                dst[i * 64 + 2] = wmma::__float_to_tf32(v.z);
                dst[i * 64 + 3] = wmma::__float_to_tf32(v.w);
            }
        }
    };

    load_chunk(0, 0);
    __syncthreads();

    int buf = 0;
    for (int kc = 0; kc < 32; kc++) {
        if (kc < 31) load_chunk(buf ^ 1, (kc + 1) * 16);
#pragma unroll
        for (int ks = 0; ks < 2; ks++) {
            wmma::fragment<wmma::matrix_a, 16, 16, 8, wmma::precision::tf32, wmma::row_major> af[4];
            wmma::fragment<wmma::matrix_b, 16, 16, 8, wmma::precision::tf32, wmma::row_major> bf[2];
#pragma unroll
            for (int i = 0; i < 4; i++)
                wmma::load_matrix_sync(af[i], &As[buf][(wm * 64 + i * 16) * 20 + ks * 8], 20);
#pragma unroll
            for (int j = 0; j < 2; j++)
                wmma::load_matrix_sync(bf[j], &Bs[buf][(ks * 8) * 132 + wn * 32 + j * 16], 132);
#pragma unroll
            for (int i = 0; i < 4; i++)
#pragma unroll
                for (int j = 0; j < 2; j++)
                    wmma::mma_sync(acc[i][j], af[i], bf[j], acc[i][j]);
        }
        __syncthreads();
        buf ^= 1;
    }

    // epilogue: add bias, write fp32
    float* stage = ((float*)As) + wid * 320;   // 16x20 per warp
#pragma unroll
    for (int i = 0; i < 4; i++) {
#pragma unroll
        for (int j = 0; j < 2; j++) {
            wmma::store_matrix_sync(stage, acc[i][j], 20, wmma::mem_row_major);
            __syncwarp();
#pragma unroll
            for (int p = 0; p < 8; p++) {
                const int e = p * 32 + lane;
                const int row = e >> 4, col = e & 15;
                const int gm = m0 + wm * 64 + i * 16 + row;
                const int gn = n0 + wn * 32 + j * 16 + col;
                g_xg[(size_t)gm * GATES + gn] = stage[row * 20 + col] + __ldg(&bias[gn]);
            }
            __syncwarp();
        }
    }
}

// ---------------- kernel 3: persistent LSTM, tf32 wmma recurrence (UNCHANGED from R4) ----------------
#define HLD    520
#define HSMF   (32 * HLD)
#define WSMF   (512 * 16)
#define REDF   (8 * 512)
#define LSTM_SMEM ((HSMF + WSMF + REDF + 512 + 128) * 4 + MTOT * 4)

__global__ __launch_bounds__(256) void lstm_persist_kernel(
    const float* __restrict__ Wh,
    const int*   __restrict__ tokens)
{
    extern __shared__ float sm[];
    float* hsm  = sm;
    float* wsm  = sm + HSMF;
    float* red  = wsm + WSMF;
    float* rsum = red + REDF;
    float* csm  = rsum + 512;
    int*   tsm  = (int*)(csm + 128);

    const int tid  = threadIdx.x;
    const int wid  = tid >> 5;
    const int jbase = blockIdx.x * 4;

    for (int idx = tid; idx < WSMF; idx += 256) {
        const int k = idx >> 4, c = idx & 15;
        wsm[idx] = wmma::__float_to_tf32(
            Wh[(size_t)k * GATES + ((c >> 2) << 9) + jbase + (c & 3)]);
    }
    if (tid < 128) {
        const int b = tid & 31, jl = tid >> 5;
        csm[tid] = g_c[b * HIDDEN + jbase + jl];
    }
    for (int idx = tid; idx < MTOT; idx += 256) tsm[idx] = tokens[idx];
    __syncthreads();

    wmma::fragment<wmma::matrix_b, 16, 16, 8, wmma::precision::tf32, wmma::row_major> bk[8];
#pragma unroll
    for (int ks = 0; ks < 8; ks++)
        wmma::load_matrix_sync(bk[ks], &wsm[(wid * 64 + ks * 8) * 16], 16);
    __syncthreads();

    for (int t = 0; t < SS; t++) {
        float x0 = 0.f, x1 = 0.f, x2 = 0.f, x3 = 0.f;
        int b_f = 0, jl_f = 0, m_f = 0;
        if (tid < 128) {
            b_f = tid & 31; jl_f = tid >> 5;
            m_f = (b_f << 6) + t;
            const size_t xb = (size_t)m_f * GATES + jbase + jl_f;
            x0 = g_xg[xb];
            x1 = g_xg[xb + 512];
            x2 = g_xg[xb + 1024];
            x3 = g_xg[xb + 1536];
        }

        {
#pragma unroll
            for (int i = 0; i < 16; i++) {
                const int idx = tid + 256 * i;
                const int b  = idx >> 7;
                const int k4 = (idx & 127) << 2;
                const float4 v = (t == 0)
                    ? *(const float4*)&g_h0[b * HIDDEN + k4]
                    : *(const float4*)&g_hs[(size_t)((b << 6) + t - 1) * HIDDEN + k4];
                *(float4*)&hsm[b * HLD + k4] = v;
            }
        }
        __syncthreads();

        wmma::fragment<wmma::accumulator, 16, 16, 8, float> acc0, acc1;
        wmma::fill_fragment(acc0, 0.f);
        wmma::fill_fragment(acc1, 0.f);
#pragma unroll
        for (int ks = 0; ks < 8; ks++) {
            const int k0 = wid * 64 + ks * 8;
            wmma::fragment<wmma::matrix_a, 16, 16, 8, wmma::precision::tf32, wmma::row_major> a0, a1;
            wmma::load_matrix_sync(a0, &hsm[k0], HLD);
            wmma::load_matrix_sync(a1, &hsm[16 * HLD + k0], HLD);
            wmma::mma_sync(acc0, a0, bk[ks], acc0);
            wmma::mma_sync(acc1, a1, bk[ks], acc1);
        }
        wmma::store_matrix_sync(&red[wid * 512],       acc0, 16, wmma::mem_row_major);
        wmma::store_matrix_sync(&red[wid * 512 + 256], acc1, 16, wmma::mem_row_major);
        __syncthreads();

        {
            float s0 = 0.f, s1 = 0.f;
            const int o = tid;
#pragma unroll
            for (int w = 0; w < 8; w++) {
                s0 += red[w * 512 + o];
                s1 += red[w * 512 + o + 256];
            }
            rsum[o] = s0; rsum[o + 256] = s1;
        }
        __syncthreads();

        if (tid < 128) {
            const int b = b_f, jl = jl_f, m = m_f;
            const int j = jbase + jl;
            const float zi = x0 + rsum[b * 16 +  0 + jl];
            const float zf = x1 + rsum[b * 16 +  4 + jl];
            const float zg = x2 + rsum[b * 16 +  8 + jl];
            const float zo = x3 + rsum[b * 16 + 12 + jl];
            const float c_old = csm[tid];
            const float si = 1.f / (1.f + expf(-zi));
            const float sf = 1.f / (1.f + expf(-zf));
            const float so = 1.f / (1.f + expf(-zo));
            const float cn = sf * c_old + si * tanhf(zg);
            const float hn = so * tanhf(cn);
            const bool msk = (tsm[m] != 0);
            const float ho = msk ? wmma::__float_to_tf32(hn) : hsm[b * HLD + j];
            const float co = msk ? cn : c_old;
            csm[tid] = co;
            g_hs[(size_t)m * HIDDEN + j] = ho;
        }

        if (t < SS - 1) {
            __threadfence();
            __syncthreads();
            if (tid == 0) {
                atomicAdd(&g_bar[t], 1u);
                while (((volatile unsigned*)g_bar)[t] < (unsigned)NCTA)
                    __nanosleep(64);
                __threadfence();
            }
            __syncthreads();
        }
    }
}

__global__ void bar_reset_kernel() {
    if (threadIdx.x < SS) g_bar[threadIdx.x] = 0;
}

// ---------------- kernel 4: logits = hs @ W_out + b_out  (tf32 wmma, BK=16) ----------------
// CTA 128x256, 8 warps, warp tile 64x64. A is already tf32 (no conversion);
// B converted once at smem store. Dynamic smem, double buffered.
#define LG_ASZ (128 * 20)
#define LG_BSZ (16 * 260)
#define LOGITS_SMEM ((LG_ASZ + LG_BSZ) * 2 * 4)   // 53760 bytes

__global__ __launch_bounds__(256) void logits_kernel(
    const float* __restrict__ Wout,
    const float* __restrict__ bout,
    float* __restrict__ out)
{
    extern __shared__ float lsm[];
    float* As0 = lsm;
    float* As1 = As0 + LG_ASZ;
    float* Bs0 = As1 + LG_ASZ;
    float* Bs1 = Bs0 + LG_BSZ;
    float* Asb[2] = {As0, As1};
    float* Bsb[2] = {Bs0, Bs1};

    const int tid  = threadIdx.x;
    const int wid  = tid >> 5;
    const int lane = tid & 31;
    const int wm = wid >> 2;
    const int wn = wid & 3;
    const int m0 = blockIdx.y * 128;
    const int n0 = blockIdx.x * 256;

    wmma::fragment<wmma::accumulator, 16, 16, 8, float> acc[4][4];
#pragma unroll
    for (int i = 0; i < 4; i++)
#pragma unroll
        for (int j = 0; j < 4; j++) wmma::fill_fragment(acc[i][j], 0.f);

    // A: row = tid>>1, two float4 at cols (tid&1)*8 {+0,+4}  (values already tf32)
    const int arow = tid >> 1;
    const int acol = (tid & 1) * 8;
    const float* aptr = g_hs + (size_t)(m0 + arow) * HIDDEN + acol;
    // B: row = tid>>4, four float4 at cols (tid&15)*4 + i*64
    const int brow = tid >> 4;
    const int bcol = (tid & 15) * 4;
    const float* bptr = Wout + (size_t)brow * VOCAB + n0 + bcol;

    auto load_chunk = [&](int buf, int k0) {
        {
            float* dst = &Asb[buf][arow * 20 + acol];
            *(float4*)(dst)     = *(const float4*)(aptr + k0);
            *(float4*)(dst + 4) = *(const float4*)(aptr + k0 + 4);
        }
        {
            float* dst = &Bsb[buf][brow * 260 + bcol];
#pragma unroll
            for (int i = 0; i < 4; i++) {
                float4 v = *(const float4*)(bptr + (size_t)k0 * VOCAB + i * 64);
                dst[i * 64 + 0] = wmma::__float_to_tf32(v.x);
                dst[i * 64 + 1] = wmma::__float_to_tf32(v.y);
                dst[i * 64 + 2] = wmma::__float_to_tf32(v.z);
                dst[i * 64 + 3] = wmma::__float_to_tf32(v.w);
            }
        }
    };

    load_chunk(0, 0);
    __syncthreads();

    int buf = 0;
    for (int kc = 0; kc < 32; kc++) {
        if (kc < 31) load_chunk(buf ^ 1, (kc + 1) * 16);
#pragma unroll
        for (int ks = 0; ks < 2; ks++) {
            wmma::fragment<wmma::matrix_a, 16, 16, 8, wmma::precision::tf32, wmma::row_major> af[4];
            wmma::fragment<wmma::matrix_b, 16, 16, 8, wmma::precision::tf32, wmma::row_major> bf[4];
#pragma unroll
            for (int i = 0; i < 4; i++)
                wmma::load_matrix_sync(af[i], &Asb[buf][(wm * 64 + i * 16) * 20 + ks * 8], 20);
#pragma unroll
            for (int j = 0; j < 4; j++)
                wmma::load_matrix_sync(bf[j], &Bsb[buf][(ks * 8) * 260 + wn * 64 + j * 16], 260);
#pragma unroll
            for (int i = 0; i < 4; i++)
#pragma unroll
                for (int j = 0; j < 4; j++)
                    wmma::mma_sync(acc[i][j], af[i], bf[j], acc[i][j]);
        }
        __syncthreads();
        buf ^= 1;
    }

    float* stage = lsm + wid * 320;   // 16x20 per warp
#pragma unroll
    for (int i = 0; i < 4; i++) {
#pragma unroll
        for (int j = 0; j < 4; j++) {
            wmma::store_matrix_sync(stage, acc[i][j], 20, wmma::mem_row_major);
            __syncwarp();
#pragma unroll
            for (int p = 0; p < 8; p++) {
                const int e = p * 32 + lane;
                const int row = e >> 4, col = e & 15;
                const int gm = m0 + wm * 64 + i * 16 + row;
                const int gn = n0 + wn * 64 + j * 16 + col;
                out[(size_t)gm * VOCAB + gn] = stage[row * 20 + col] + __ldg(&bout[gn]);
            }
            __syncwarp();
        }
    }
}

// ---------------- launch ----------------
extern "C" void kernel_launch(void* const* d_in, const int* in_sizes, int n_in,
                              void* d_out, int out_size)
{
    const int*   tokens  = (const int*)  d_in[0];
    const float* context = (const float*)d_in[1];
    const float* emb     = (const float*)d_in[2];
    const float* W_ih    = (const float*)d_in[3];
    const float* b_ih    = (const float*)d_in[4];
    const float* W_ic    = (const float*)d_in[5];
    const float* b_ic    = (const float*)d_in[6];
    const float* W_x     = (const float*)d_in[7];
    const float* W_h     = (const float*)d_in[8];
    const float* b_g     = (const float*)d_in[9];
    const float* W_out   = (const float*)d_in[10];
    const float* b_out   = (const float*)d_in[11];
    float* out = (float*)d_out;

    cudaFuncSetAttribute(lstm_persist_kernel,
                         cudaFuncAttributeMaxDynamicSharedMemorySize, LSTM_SMEM);
    cudaFuncSetAttribute(logits_kernel,
                         cudaFuncAttributeMaxDynamicSharedMemorySize, LOGITS_SMEM);

    init_gemm_kernel<<<16, 128>>>(context, W_ih, b_ih, W_ic, b_ic);
    xg_kernel<<<dim3(16, 16), 256>>>(tokens, emb, W_x, b_g);
    bar_reset_kernel<<<1, 64>>>();
    lstm_persist_kernel<<<NCTA, 256, LSTM_SMEM>>>(W_h, tokens);
    logits_kernel<<<dim3(125, 16), 256, LOGITS_SMEM>>>(W_out, b_out, out);
}

// round 8
// speedup vs baseline: 2.3610x; 1.8220x over previous
#include <cuda_runtime.h>
#include <cuda_bf16.h>
#include <cuda_fp16.h>
#include <mma.h>

using namespace nvcuda;

#define VOCAB  32000
#define EMBED  512
#define HIDDEN 512
#define CTXD   2048
#define BB     32
#define SS     64
#define MTOT   (BB * SS)      // 2048
#define GATES  (4 * HIDDEN)   // 2048
#define NCTA   128

// ---------------- scratch (device globals; no allocation allowed) ----------------
__device__ float g_xg[MTOT * GATES];        // 16 MB : xg = emb@W_x + b
__device__ float g_hs[MTOT * HIDDEN];       // 4 MB  : h per step (tf32 values in fp32)
__device__ float g_h0[BB * HIDDEN];         // [b][j], tf32-rounded
__device__ float g_c [BB * HIDDEN];
__device__ unsigned g_bar[SS];              // per-step grid barrier counters

// ---------------- kernel 1: [h0|c0] = tanh(ctx @ [W_ih|W_ic] + bias)  (tf32 wmma) ----------------
__global__ __launch_bounds__(128) void init_gemm_kernel(
    const float* __restrict__ context,
    const float* __restrict__ W_ih, const float* __restrict__ b_ih,
    const float* __restrict__ W_ic, const float* __restrict__ b_ic)
{
    __shared__ float Asm[32 * 68];
    __shared__ float Bsm[64 * 68];

    const int tid = threadIdx.x;
    const int wid = tid >> 5;
    const int lane = tid & 31;
    const int n0 = blockIdx.x * 64;
    const bool which = (n0 >= 512);
    const int ncol = n0 & 511;
    const float* W  = which ? W_ic : W_ih;
    const float* bv = which ? b_ic : b_ih;

    wmma::fragment<wmma::accumulator, 16, 16, 8, float> acc0, acc1;
    wmma::fill_fragment(acc0, 0.f);
    wmma::fill_fragment(acc1, 0.f);

    for (int kc = 0; kc < 32; kc++) {
        const int k0 = kc * 64;
        {
            const int row = tid >> 2;
            const int cb  = (tid & 3) * 16;
            const float* src = context + (size_t)row * CTXD + k0 + cb;
            float* dst = Asm + row * 68 + cb;
#pragma unroll
            for (int i = 0; i < 4; i++) {
                float4 v = *(const float4*)(src + i * 4);
                dst[i * 4 + 0] = wmma::__float_to_tf32(v.x);
                dst[i * 4 + 1] = wmma::__float_to_tf32(v.y);
                dst[i * 4 + 2] = wmma::__float_to_tf32(v.z);
                dst[i * 4 + 3] = wmma::__float_to_tf32(v.w);
            }
        }
        {
            const int r  = tid >> 1;
            const int c0 = (tid & 1) * 4;
            const float* src = W + (size_t)(k0 + r) * HIDDEN + ncol + c0;
            float* dst = Bsm + r * 68 + c0;
#pragma unroll
            for (int i = 0; i < 8; i++) {
                float4 v = *(const float4*)(src + i * 8);
                dst[i * 8 + 0] = wmma::__float_to_tf32(v.x);
                dst[i * 8 + 1] = wmma::__float_to_tf32(v.y);
                dst[i * 8 + 2] = wmma::__float_to_tf32(v.z);
                dst[i * 8 + 3] = wmma::__float_to_tf32(v.w);
            }
        }
        __syncthreads();
#pragma unroll
        for (int ks = 0; ks < 8; ks++) {
            wmma::fragment<wmma::matrix_a, 16, 16, 8, wmma::precision::tf32, wmma::row_major> a0, a1;
            wmma::fragment<wmma::matrix_b, 16, 16, 8, wmma::precision::tf32, wmma::row_major> bf;
            wmma::load_matrix_sync(a0, &Asm[ks * 8], 68);
            wmma::load_matrix_sync(a1, &Asm[16 * 68 + ks * 8], 68);
            wmma::load_matrix_sync(bf, &Bsm[(ks * 8) * 68 + wid * 16], 68);
            wmma::mma_sync(acc0, a0, bf, acc0);
            wmma::mma_sync(acc1, a1, bf, acc1);
        }
        __syncthreads();
    }

    float* stage = Asm + wid * 640;
    wmma::store_matrix_sync(stage, acc0, 20, wmma::mem_row_major);
    wmma::store_matrix_sync(stage + 16 * 20, acc1, 20, wmma::mem_row_major);
    __syncwarp();
#pragma unroll
    for (int p = 0; p < 16; p++) {
        const int e = p * 32 + lane;
        const int r = e >> 4, c = e & 15;
        const int j = ncol + wid * 16 + c;
        const float v = tanhf(stage[r * 20 + c] + bv[j]);
        if (which) g_c [r * HIDDEN + j] = v;
        else       g_h0[r * HIDDEN + j] = wmma::__float_to_tf32(v);
    }
}

// ---------------- kernel 2: xg = gather(emb)@W_x + b  (tf32 wmma) ----------------
__global__ __launch_bounds__(256) void xg_kernel(
    const int*   __restrict__ tokens,
    const float* __restrict__ emb,
    const float* __restrict__ Wx,
    const float* __restrict__ bias)
{
    __shared__ float As[2][128 * 20];
    __shared__ float Bs[2][16 * 132];

    const int tid = threadIdx.x;
    const int wid = tid >> 5;
    const int lane = tid & 31;
    const int wm = wid >> 2;
    const int wn = wid & 3;
    const int m0 = blockIdx.y * 128, n0 = blockIdx.x * 128;

    const int arow = tid >> 1;
    const int acol = (tid & 1) * 8;
    const int tok  = tokens[m0 + arow];
    const float* aptr = emb + (size_t)tok * EMBED + acol;
    const int brow = tid >> 4;
    const int bcol = (tid & 15) * 4;
    const float* bptr = Wx + (size_t)brow * GATES + n0 + bcol;

    wmma::fragment<wmma::accumulator, 16, 16, 8, float> acc[4][2];
#pragma unroll
    for (int i = 0; i < 4; i++)
#pragma unroll
        for (int j = 0; j < 2; j++) wmma::fill_fragment(acc[i][j], 0.f);

    auto load_chunk = [&](int buf, int k0) {
        {
            float* dst = &As[buf][arow * 20 + acol];
            float4 v0 = *(const float4*)(aptr + k0);
            float4 v1 = *(const float4*)(aptr + k0 + 4);
            dst[0] = wmma::__float_to_tf32(v0.x); dst[1] = wmma::__float_to_tf32(v0.y);
            dst[2] = wmma::__float_to_tf32(v0.z); dst[3] = wmma::__float_to_tf32(v0.w);
            dst[4] = wmma::__float_to_tf32(v1.x); dst[5] = wmma::__float_to_tf32(v1.y);
            dst[6] = wmma::__float_to_tf32(v1.z); dst[7] = wmma::__float_to_tf32(v1.w);
        }
        {
            float* dst = &Bs[buf][brow * 132 + bcol];
#pragma unroll
            for (int i = 0; i < 2; i++) {
                float4 v = *(const float4*)(bptr + (size_t)k0 * GATES + i * 64);
                dst[i * 64 + 0] = wmma::__float_to_tf32(v.x);
                dst[i * 64 + 1] = wmma::__float_to_tf32(v.y);
                dst[i * 64 + 2] = wmma::__float_to_tf32(v.z);
                dst[i * 64 + 3] = wmma::__float_to_tf32(v.w);
            }
        }
    };

    load_chunk(0, 0);
    __syncthreads();

    int buf = 0;
    for (int kc = 0; kc < 32; kc++) {
        if (kc < 31) load_chunk(buf ^ 1, (kc + 1) * 16);
#pragma unroll
        for (int ks = 0; ks < 2; ks++) {
            wmma::fragment<wmma::matrix_a, 16, 16, 8, wmma::precision::tf32, wmma::row_major> af[4];
            wmma::fragment<wmma::matrix_b, 16, 16, 8, wmma::precision::tf32, wmma::row_major> bf[2];
#pragma unroll
            for (int i = 0; i < 4; i++)
                wmma::load_matrix_sync(af[i], &As[buf][(wm * 64 + i * 16) * 20 + ks * 8], 20);
#pragma unroll
            for (int j = 0; j < 2; j++)
                wmma::load_matrix_sync(bf[j], &Bs[buf][(ks * 8) * 132 + wn * 32 + j * 16], 132);
#pragma unroll
            for (int i = 0; i < 4; i++)
#pragma unroll
                for (int j = 0; j < 2; j++)
                    wmma::mma_sync(acc[i][j], af[i], bf[j], acc[i][j]);
        }
        __syncthreads();
        buf ^= 1;
    }

    float* stage = ((float*)As) + wid * 320;
#pragma unroll
    for (int i = 0; i < 4; i++) {
#pragma unroll
        for (int j = 0; j < 2; j++) {
            wmma::store_matrix_sync(stage, acc[i][j], 20, wmma::mem_row_major);
            __syncwarp();
#pragma unroll
            for (int p = 0; p < 8; p++) {
                const int e = p * 32 + lane;
                const int row = e >> 4, col = e & 15;
                const int gm = m0 + wm * 64 + i * 16 + row;
                const int gn = n0 + wn * 32 + j * 16 + col;
                g_xg[(size_t)gm * GATES + gn] = stage[row * 20 + col] + __ldg(&bias[gn]);
            }
            __syncwarp();
        }
    }
}

// ---------------- kernel 3: persistent LSTM (UNCHANGED) ----------------
#define HLD    520
#define HSMF   (32 * HLD)
#define WSMF   (512 * 16)
#define REDF   (8 * 512)
#define LSTM_SMEM ((HSMF + WSMF + REDF + 512 + 128) * 4 + MTOT * 4)

__global__ __launch_bounds__(256) void lstm_persist_kernel(
    const float* __restrict__ Wh,
    const int*   __restrict__ tokens)
{
    extern __shared__ float sm[];
    float* hsm  = sm;
    float* wsm  = sm + HSMF;
    float* red  = wsm + WSMF;
    float* rsum = red + REDF;
    float* csm  = rsum + 512;
    int*   tsm  = (int*)(csm + 128);

    const int tid  = threadIdx.x;
    const int wid  = tid >> 5;
    const int jbase = blockIdx.x * 4;

    for (int idx = tid; idx < WSMF; idx += 256) {
        const int k = idx >> 4, c = idx & 15;
        wsm[idx] = wmma::__float_to_tf32(
            Wh[(size_t)k * GATES + ((c >> 2) << 9) + jbase + (c & 3)]);
    }
    if (tid < 128) {
        const int b = tid & 31, jl = tid >> 5;
        csm[tid] = g_c[b * HIDDEN + jbase + jl];
    }
    for (int idx = tid; idx < MTOT; idx += 256) tsm[idx] = tokens[idx];
    __syncthreads();

    wmma::fragment<wmma::matrix_b, 16, 16, 8, wmma::precision::tf32, wmma::row_major> bk[8];
#pragma unroll
    for (int ks = 0; ks < 8; ks++)
        wmma::load_matrix_sync(bk[ks], &wsm[(wid * 64 + ks * 8) * 16], 16);
    __syncthreads();

    for (int t = 0; t < SS; t++) {
        float x0 = 0.f, x1 = 0.f, x2 = 0.f, x3 = 0.f;
        int b_f = 0, jl_f = 0, m_f = 0;
        if (tid < 128) {
            b_f = tid & 31; jl_f = tid >> 5;
            m_f = (b_f << 6) + t;
            const size_t xb = (size_t)m_f * GATES + jbase + jl_f;
            x0 = g_xg[xb];
            x1 = g_xg[xb + 512];
            x2 = g_xg[xb + 1024];
            x3 = g_xg[xb + 1536];
        }

        {
#pragma unroll
            for (int i = 0; i < 16; i++) {
                const int idx = tid + 256 * i;
                const int b  = idx >> 7;
                const int k4 = (idx & 127) << 2;
                const float4 v = (t == 0)
                    ? *(const float4*)&g_h0[b * HIDDEN + k4]
                    : *(const float4*)&g_hs[(size_t)((b << 6) + t - 1) * HIDDEN + k4];
                *(float4*)&hsm[b * HLD + k4] = v;
            }
        }
        __syncthreads();

        wmma::fragment<wmma::accumulator, 16, 16, 8, float> acc0, acc1;
        wmma::fill_fragment(acc0, 0.f);
        wmma::fill_fragment(acc1, 0.f);
#pragma unroll
        for (int ks = 0; ks < 8; ks++) {
            const int k0 = wid * 64 + ks * 8;
            wmma::fragment<wmma::matrix_a, 16, 16, 8, wmma::precision::tf32, wmma::row_major> a0, a1;
            wmma::load_matrix_sync(a0, &hsm[k0], HLD);
            wmma::load_matrix_sync(a1, &hsm[16 * HLD + k0], HLD);
            wmma::mma_sync(acc0, a0, bk[ks], acc0);
            wmma::mma_sync(acc1, a1, bk[ks], acc1);
        }
        wmma::store_matrix_sync(&red[wid * 512],       acc0, 16, wmma::mem_row_major);
        wmma::store_matrix_sync(&red[wid * 512 + 256], acc1, 16, wmma::mem_row_major);
        __syncthreads();

        {
            float s0 = 0.f, s1 = 0.f;
            const int o = tid;
#pragma unroll
            for (int w = 0; w < 8; w++) {
                s0 += red[w * 512 + o];
                s1 += red[w * 512 + o + 256];
            }
            rsum[o] = s0; rsum[o + 256] = s1;
        }
        __syncthreads();

        if (tid < 128) {
            const int b = b_f, jl = jl_f, m = m_f;
            const int j = jbase + jl;
            const float zi = x0 + rsum[b * 16 +  0 + jl];
            const float zf = x1 + rsum[b * 16 +  4 + jl];
            const float zg = x2 + rsum[b * 16 +  8 + jl];
            const float zo = x3 + rsum[b * 16 + 12 + jl];
            const float c_old = csm[tid];
            const float si = 1.f / (1.f + expf(-zi));
            const float sf = 1.f / (1.f + expf(-zf));
            const float so = 1.f / (1.f + expf(-zo));
            const float cn = sf * c_old + si * tanhf(zg);
            const float hn = so * tanhf(cn);
            const bool msk = (tsm[m] != 0);
            const float ho = msk ? wmma::__float_to_tf32(hn) : hsm[b * HLD + j];
            const float co = msk ? cn : c_old;
            csm[tid] = co;
            g_hs[(size_t)m * HIDDEN + j] = ho;
        }

        if (t < SS - 1) {
            __threadfence();
            __syncthreads();
            if (tid == 0) {
                atomicAdd(&g_bar[t], 1u);
                while (((volatile unsigned*)g_bar)[t] < (unsigned)NCTA)
                    __nanosleep(64);
                __threadfence();
            }
            __syncthreads();
        }
    }
}

__global__ void bar_reset_kernel() {
    if (threadIdx.x < SS) g_bar[threadIdx.x] = 0;
}

// ---------------- kernel 4: logits = hs @ W_out + b_out  (fp16 wmma m16n16k16) ----------------
// CTA 128x128, BK=32, 8 warps, warp tile 32x64, 2 CTAs/SM. fp32 accumulate.
#define LG_ALD 40     // 32 + 8 pad (halfs)
#define LG_BLD 136    // 128 + 8 pad (halfs)

__global__ __launch_bounds__(256, 2) void logits_kernel(
    const float* __restrict__ Wout,
    const float* __restrict__ bout,
    float* __restrict__ out)
{
    __shared__ __half As[2][128 * LG_ALD];   // 20480 B
    __shared__ __half Bs[2][32 * LG_BLD];    // 17408 B

    const int tid  = threadIdx.x;
    const int wid  = tid >> 5;
    const int lane = tid & 31;
    const int wm = wid & 3;             // m quarter (32 rows)
    const int wn = wid >> 2;            // n half (64 cols)
    const int m0 = blockIdx.y * 128;
    const int n0 = blockIdx.x * 128;

    wmma::fragment<wmma::accumulator, 16, 16, 16, float> acc[2][4];
#pragma unroll
    for (int i = 0; i < 2; i++)
#pragma unroll
        for (int j = 0; j < 4; j++) wmma::fill_fragment(acc[i][j], 0.f);

    // A: 128 rows x 32 k-cols. thread: row = tid>>1, colbase = (tid&1)*16, 4x float4
    const int arow = tid >> 1;
    const int acb  = (tid & 1) * 16;
    const float* aptr = g_hs + (size_t)(m0 + arow) * HIDDEN + acb;
    // B: 32 k-rows x 128 n-cols. thread: row = tid>>3, colbase = (tid&7)*4, 4x float4 at +i*32
    const int brow = tid >> 3;
    const int bcb  = (tid & 7) * 4;
    const float* bptr = Wout + (size_t)brow * VOCAB + n0 + bcb;

    auto load_chunk = [&](int buf, int k0) {
        {
            __half* dst = &As[buf][arow * LG_ALD + acb];
#pragma unroll
            for (int i = 0; i < 4; i++) {
                float4 v = *(const float4*)(aptr + k0 + i * 4);
                *(__half2*)(dst + i * 4)     = __floats2half2_rn(v.x, v.y);
                *(__half2*)(dst + i * 4 + 2) = __floats2half2_rn(v.z, v.w);
            }
        }
        {
            __half* dst = &Bs[buf][brow * LG_BLD + bcb];
            const float* src = bptr + (size_t)k0 * VOCAB;
#pragma unroll
            for (int i = 0; i < 4; i++) {
                float4 v = *(const float4*)(src + i * 32);
                *(__half2*)(dst + i * 32)     = __floats2half2_rn(v.x, v.y);
                *(__half2*)(dst + i * 32 + 2) = __floats2half2_rn(v.z, v.w);
            }
        }
    };

    load_chunk(0, 0);
    __syncthreads();

    int buf = 0;
#pragma unroll 1
    for (int kc = 0; kc < 16; kc++) {
        if (kc < 15) load_chunk(buf ^ 1, (kc + 1) * 32);
#pragma unroll
        for (int ks = 0; ks < 2; ks++) {
            wmma::fragment<wmma::matrix_a, 16, 16, 16, __half, wmma::row_major> af[2];
            wmma::fragment<wmma::matrix_b, 16, 16, 16, __half, wmma::row_major> bf[4];
#pragma unroll
            for (int i = 0; i < 2; i++)
                wmma::load_matrix_sync(af[i], &As[buf][(wm * 32 + i * 16) * LG_ALD + ks * 16], LG_ALD);
#pragma unroll
            for (int j = 0; j < 4; j++)
                wmma::load_matrix_sync(bf[j], &Bs[buf][(ks * 16) * LG_BLD + wn * 64 + j * 16], LG_BLD);
#pragma unroll
            for (int i = 0; i < 2; i++)
#pragma unroll
                for (int j = 0; j < 4; j++)
                    wmma::mma_sync(acc[i][j], af[i], bf[j], acc[i][j]);
        }
        __syncthreads();
        buf ^= 1;
    }

    // epilogue: stage per warp, add bias, write
    float* stage = ((float*)As) + wid * 320;   // 16x20 per warp (reuses A buffers)
#pragma unroll
    for (int i = 0; i < 2; i++) {
#pragma unroll
        for (int j = 0; j < 4; j++) {
            wmma::store_matrix_sync(stage, acc[i][j], 20, wmma::mem_row_major);
            __syncwarp();
#pragma unroll
            for (int p = 0; p < 8; p++) {
                const int e = p * 32 + lane;
                const int row = e >> 4, col = e & 15;
                const int gm = m0 + wm * 32 + i * 16 + row;
                const int gn = n0 + wn * 64 + j * 16 + col;
                out[(size_t)gm * VOCAB + gn] = stage[row * 20 + col] + __ldg(&bout[gn]);
            }
            __syncwarp();
        }
    }
}

// ---------------- launch ----------------
extern "C" void kernel_launch(void* const* d_in, const int* in_sizes, int n_in,
                              void* d_out, int out_size)
{
    const int*   tokens  = (const int*)  d_in[0];
    const float* context = (const float*)d_in[1];
    const float* emb     = (const float*)d_in[2];
    const float* W_ih    = (const float*)d_in[3];
    const float* b_ih    = (const float*)d_in[4];
    const float* W_ic    = (const float*)d_in[5];
    const float* b_ic    = (const float*)d_in[6];
    const float* W_x     = (const float*)d_in[7];
    const float* W_h     = (const float*)d_in[8];
    const float* b_g     = (const float*)d_in[9];
    const float* W_out   = (const float*)d_in[10];
    const float* b_out   = (const float*)d_in[11];
    float* out = (float*)d_out;

    cudaFuncSetAttribute(lstm_persist_kernel,
                         cudaFuncAttributeMaxDynamicSharedMemorySize, LSTM_SMEM);

    // order chosen so the profiled (4th) launch is the logits GEMM
    init_gemm_kernel<<<16, 128>>>(context, W_ih, b_ih, W_ic, b_ic);
    xg_kernel<<<dim3(16, 16), 256>>>(tokens, emb, W_x, b_g);
    lstm_persist_kernel<<<NCTA, 256, LSTM_SMEM>>>(W_h, tokens);
    logits_kernel<<<dim3(250, 16), 256>>>(W_out, b_out, out);
    bar_reset_kernel<<<1, 64>>>();   // reset counters for next replay (globals start zeroed)
}

// round 10
// speedup vs baseline: 2.4231x; 1.0263x over previous
#include <cuda_runtime.h>
#include <cuda_bf16.h>
#include <cuda_fp16.h>
#include <mma.h>

using namespace nvcuda;

#define VOCAB  32000
#define EMBED  512
#define HIDDEN 512
#define CTXD   2048
#define BB     32
#define SS     64
#define MTOT   (BB * SS)      // 2048
#define GATES  (4 * HIDDEN)   // 2048
#define NCTA   128

// ---------------- scratch (device globals; no allocation allowed) ----------------
__device__ float g_xg[MTOT * GATES];        // 16 MB
__device__ float g_hs[MTOT * HIDDEN];       // 4 MB (tf32 values in fp32)
__device__ float g_h0[BB * HIDDEN];
__device__ float g_c [BB * HIDDEN];
__device__ float g_bias16[16 * VOCAB];      // 2 MB : b_out replicated over 16 rows
__device__ unsigned g_bar[SS];

// ---------------- kernel 0: replicate b_out into 16 rows ----------------
__global__ void bias_rep_kernel(const float* __restrict__ bout) {
    const int idx = blockIdx.x * 256 + threadIdx.x;
    if (idx < 16 * VOCAB) g_bias16[idx] = bout[idx % VOCAB];
}

// ---------------- kernel 1: [h0|c0] = tanh(ctx @ [W_ih|W_ic] + bias)  (tf32 wmma) ----------------
__global__ __launch_bounds__(128) void init_gemm_kernel(
    const float* __restrict__ context,
    const float* __restrict__ W_ih, const float* __restrict__ b_ih,
    const float* __restrict__ W_ic, const float* __restrict__ b_ic)
{
    __shared__ float Asm[32 * 68];
    __shared__ float Bsm[64 * 68];

    const int tid = threadIdx.x;
    const int wid = tid >> 5;
    const int lane = tid & 31;
    const int n0 = blockIdx.x * 64;
    const bool which = (n0 >= 512);
    const int ncol = n0 & 511;
    const float* W  = which ? W_ic : W_ih;
    const float* bv = which ? b_ic : b_ih;

    wmma::fragment<wmma::accumulator, 16, 16, 8, float> acc0, acc1;
    wmma::fill_fragment(acc0, 0.f);
    wmma::fill_fragment(acc1, 0.f);

    for (int kc = 0; kc < 32; kc++) {
        const int k0 = kc * 64;
        {
            const int row = tid >> 2;
            const int cb  = (tid & 3) * 16;
            const float* src = context + (size_t)row * CTXD + k0 + cb;
            float* dst = Asm + row * 68 + cb;
#pragma unroll
            for (int i = 0; i < 4; i++) {
                float4 v = *(const float4*)(src + i * 4);
                dst[i * 4 + 0] = wmma::__float_to_tf32(v.x);
                dst[i * 4 + 1] = wmma::__float_to_tf32(v.y);
                dst[i * 4 + 2] = wmma::__float_to_tf32(v.z);
                dst[i * 4 + 3] = wmma::__float_to_tf32(v.w);
            }
        }
        {
            const int r  = tid >> 1;
            const int c0 = (tid & 1) * 4;
            const float* src = W + (size_t)(k0 + r) * HIDDEN + ncol + c0;
            float* dst = Bsm + r * 68 + c0;
#pragma unroll
            for (int i = 0; i < 8; i++) {
                float4 v = *(const float4*)(src + i * 8);
                dst[i * 8 + 0] = wmma::__float_to_tf32(v.x);
                dst[i * 8 + 1] = wmma::__float_to_tf32(v.y);
                dst[i * 8 + 2] = wmma::__float_to_tf32(v.z);
                dst[i * 8 + 3] = wmma::__float_to_tf32(v.w);
            }
        }
        __syncthreads();
#pragma unroll
        for (int ks = 0; ks < 8; ks++) {
            wmma::fragment<wmma::matrix_a, 16, 16, 8, wmma::precision::tf32, wmma::row_major> a0, a1;
            wmma::fragment<wmma::matrix_b, 16, 16, 8, wmma::precision::tf32, wmma::row_major> bf;
            wmma::load_matrix_sync(a0, &Asm[ks * 8], 68);
            wmma::load_matrix_sync(a1, &Asm[16 * 68 + ks * 8], 68);
            wmma::load_matrix_sync(bf, &Bsm[(ks * 8) * 68 + wid * 16], 68);
            wmma::mma_sync(acc0, a0, bf, acc0);
            wmma::mma_sync(acc1, a1, bf, acc1);
        }
        __syncthreads();
    }

    float* stage = Asm + wid * 640;
    wmma::store_matrix_sync(stage, acc0, 20, wmma::mem_row_major);
    wmma::store_matrix_sync(stage + 16 * 20, acc1, 20, wmma::mem_row_major);
    __syncwarp();
#pragma unroll
    for (int p = 0; p < 16; p++) {
        const int e = p * 32 + lane;
        const int r = e >> 4, c = e & 15;
        const int j = ncol + wid * 16 + c;
        const float v = tanhf(stage[r * 20 + c] + bv[j]);
        if (which) g_c [r * HIDDEN + j] = v;
        else       g_h0[r * HIDDEN + j] = wmma::__float_to_tf32(v);
    }
}

// ---------------- kernel 2: xg = gather(emb)@W_x + b  (tf32 wmma) ----------------
__global__ __launch_bounds__(256) void xg_kernel(
    const int*   __restrict__ tokens,
    const float* __restrict__ emb,
    const float* __restrict__ Wx,
    const float* __restrict__ bias)
{
    __shared__ float As[2][128 * 20];
    __shared__ float Bs[2][16 * 132];

    const int tid = threadIdx.x;
    const int wid = tid >> 5;
    const int lane = tid & 31;
    const int wm = wid >> 2;
    const int wn = wid & 3;
    const int m0 = blockIdx.y * 128, n0 = blockIdx.x * 128;

    const int arow = tid >> 1;
    const int acol = (tid & 1) * 8;
    const int tok  = tokens[m0 + arow];
    const float* aptr = emb + (size_t)tok * EMBED + acol;
    const int brow = tid >> 4;
    const int bcol = (tid & 15) * 4;
    const float* bptr = Wx + (size_t)brow * GATES + n0 + bcol;

    wmma::fragment<wmma::accumulator, 16, 16, 8, float> acc[4][2];
#pragma unroll
    for (int i = 0; i < 4; i++)
#pragma unroll
        for (int j = 0; j < 2; j++) wmma::fill_fragment(acc[i][j], 0.f);

    auto load_chunk = [&](int buf, int k0) {
        {
            float* dst = &As[buf][arow * 20 + acol];
            float4 v0 = *(const float4*)(aptr + k0);
            float4 v1 = *(const float4*)(aptr + k0 + 4);
            dst[0] = wmma::__float_to_tf32(v0.x); dst[1] = wmma::__float_to_tf32(v0.y);
            dst[2] = wmma::__float_to_tf32(v0.z); dst[3] = wmma::__float_to_tf32(v0.w);
            dst[4] = wmma::__float_to_tf32(v1.x); dst[5] = wmma::__float_to_tf32(v1.y);
            dst[6] = wmma::__float_to_tf32(v1.z); dst[7] = wmma::__float_to_tf32(v1.w);
        }
        {
            float* dst = &Bs[buf][brow * 132 + bcol];
#pragma unroll
            for (int i = 0; i < 2; i++) {
                float4 v = *(const float4*)(bptr + (size_t)k0 * GATES + i * 64);
                dst[i * 64 + 0] = wmma::__float_to_tf32(v.x);
                dst[i * 64 + 1] = wmma::__float_to_tf32(v.y);
                dst[i * 64 + 2] = wmma::__float_to_tf32(v.z);
                dst[i * 64 + 3] = wmma::__float_to_tf32(v.w);
            }
        }
    };

    load_chunk(0, 0);
    __syncthreads();

    int buf = 0;
    for (int kc = 0; kc < 32; kc++) {
        if (kc < 31) load_chunk(buf ^ 1, (kc + 1) * 16);
#pragma unroll
        for (int ks = 0; ks < 2; ks++) {
            wmma::fragment<wmma::matrix_a, 16, 16, 8, wmma::precision::tf32, wmma::row_major> af[4];
            wmma::fragment<wmma::matrix_b, 16, 16, 8, wmma::precision::tf32, wmma::row_major> bf[2];
#pragma unroll
            for (int i = 0; i < 4; i++)
                wmma::load_matrix_sync(af[i], &As[buf][(wm * 64 + i * 16) * 20 + ks * 8], 20);
#pragma unroll
            for (int j = 0; j < 2; j++)
                wmma::load_matrix_sync(bf[j], &Bs[buf][(ks * 8) * 132 + wn * 32 + j * 16], 132);
#pragma unroll
            for (int i = 0; i < 4; i++)
#pragma unroll
                for (int j = 0; j < 2; j++)
                    wmma::mma_sync(acc[i][j], af[i], bf[j], acc[i][j]);
        }
        __syncthreads();
        buf ^= 1;
    }

    float* stage = ((float*)As) + wid * 320;
#pragma unroll
    for (int i = 0; i < 4; i++) {
#pragma unroll
        for (int j = 0; j < 2; j++) {
            wmma::store_matrix_sync(stage, acc[i][j], 20, wmma::mem_row_major);
            __syncwarp();
#pragma unroll
            for (int p = 0; p < 8; p++) {
                const int e = p * 32 + lane;
                const int row = e >> 4, col = e & 15;
                const int gm = m0 + wm * 64 + i * 16 + row;
                const int gn = n0 + wn * 32 + j * 16 + col;
                g_xg[(size_t)gm * GATES + gn] = stage[row * 20 + col] + __ldg(&bias[gn]);
            }
            __syncwarp();
        }
    }
}

// ---------------- kernel 3: persistent LSTM (UNCHANGED) ----------------
#define HLD    520
#define HSMF   (32 * HLD)
#define WSMF   (512 * 16)
#define REDF   (8 * 512)
#define LSTM_SMEM ((HSMF + WSMF + REDF + 512 + 128) * 4 + MTOT * 4)

__global__ __launch_bounds__(256) void lstm_persist_kernel(
    const float* __restrict__ Wh,
    const int*   __restrict__ tokens)
{
    extern __shared__ float sm[];
    float* hsm  = sm;
    float* wsm  = sm + HSMF;
    float* red  = wsm + WSMF;
    float* rsum = red + REDF;
    float* csm  = rsum + 512;
    int*   tsm  = (int*)(csm + 128);

    const int tid  = threadIdx.x;
    const int wid  = tid >> 5;
    const int jbase = blockIdx.x * 4;

    for (int idx = tid; idx < WSMF; idx += 256) {
        const int k = idx >> 4, c = idx & 15;
        wsm[idx] = wmma::__float_to_tf32(
            Wh[(size_t)k * GATES + ((c >> 2) << 9) + jbase + (c & 3)]);
    }
    if (tid < 128) {
        const int b = tid & 31, jl = tid >> 5;
        csm[tid] = g_c[b * HIDDEN + jbase + jl];
    }
    for (int idx = tid; idx < MTOT; idx += 256) tsm[idx] = tokens[idx];
    __syncthreads();

    wmma::fragment<wmma::matrix_b, 16, 16, 8, wmma::precision::tf32, wmma::row_major> bk[8];
#pragma unroll
    for (int ks = 0; ks < 8; ks++)
        wmma::load_matrix_sync(bk[ks], &wsm[(wid * 64 + ks * 8) * 16], 16);
    __syncthreads();

    for (int t = 0; t < SS; t++) {
        float x0 = 0.f, x1 = 0.f, x2 = 0.f, x3 = 0.f;
        int b_f = 0, jl_f = 0, m_f = 0;
        if (tid < 128) {
            b_f = tid & 31; jl_f = tid >> 5;
            m_f = (b_f << 6) + t;
            const size_t xb = (size_t)m_f * GATES + jbase + jl_f;
            x0 = g_xg[xb];
            x1 = g_xg[xb + 512];
            x2 = g_xg[xb + 1024];
            x3 = g_xg[xb + 1536];
        }

        {
#pragma unroll
            for (int i = 0; i < 16; i++) {
                const int idx = tid + 256 * i;
                const int b  = idx >> 7;
                const int k4 = (idx & 127) << 2;
                const float4 v = (t == 0)
                    ? *(const float4*)&g_h0[b * HIDDEN + k4]
                    : *(const float4*)&g_hs[(size_t)((b << 6) + t - 1) * HIDDEN + k4];
                *(float4*)&hsm[b * HLD + k4] = v;
            }
        }
        __syncthreads();

        wmma::fragment<wmma::accumulator, 16, 16, 8, float> acc0, acc1;
        wmma::fill_fragment(acc0, 0.f);
        wmma::fill_fragment(acc1, 0.f);
#pragma unroll
        for (int ks = 0; ks < 8; ks++) {
            const int k0 = wid * 64 + ks * 8;
            wmma::fragment<wmma::matrix_a, 16, 16, 8, wmma::precision::tf32, wmma::row_major> a0, a1;
            wmma::load_matrix_sync(a0, &hsm[k0], HLD);
            wmma::load_matrix_sync(a1, &hsm[16 * HLD + k0], HLD);
            wmma::mma_sync(acc0, a0, bk[ks], acc0);
            wmma::mma_sync(acc1, a1, bk[ks], acc1);
        }
        wmma::store_matrix_sync(&red[wid * 512],       acc0, 16, wmma::mem_row_major);
        wmma::store_matrix_sync(&red[wid * 512 + 256], acc1, 16, wmma::mem_row_major);
        __syncthreads();

        {
            float s0 = 0.f, s1 = 0.f;
            const int o = tid;
#pragma unroll
            for (int w = 0; w < 8; w++) {
                s0 += red[w * 512 + o];
                s1 += red[w * 512 + o + 256];
            }
            rsum[o] = s0; rsum[o + 256] = s1;
        }
        __syncthreads();

        if (tid < 128) {
            const int b = b_f, jl = jl_f, m = m_f;
            const int j = jbase + jl;
            const float zi = x0 + rsum[b * 16 +  0 + jl];
            const float zf = x1 + rsum[b * 16 +  4 + jl];
            const float zg = x2 + rsum[b * 16 +  8 + jl];
            const float zo = x3 + rsum[b * 16 + 12 + jl];
            const float c_old = csm[tid];
            const float si = 1.f / (1.f + expf(-zi));
            const float sf = 1.f / (1.f + expf(-zf));
            const float so = 1.f / (1.f + expf(-zo));
            const float cn = sf * c_old + si * tanhf(zg);
            const float hn = so * tanhf(cn);
            const bool msk = (tsm[m] != 0);
            const float ho = msk ? wmma::__float_to_tf32(hn) : hsm[b * HLD + j];
            const float co = msk ? cn : c_old;
            csm[tid] = co;
            g_hs[(size_t)m * HIDDEN + j] = ho;
        }

        if (t < SS - 1) {
            __threadfence();
            __syncthreads();
            if (tid == 0) {
                atomicAdd(&g_bar[t], 1u);
                while (((volatile unsigned*)g_bar)[t] < (unsigned)NCTA)
                    __nanosleep(64);
                __threadfence();
            }
            __syncthreads();
        }
    }
}

__global__ void bar_reset_kernel() {
    if (threadIdx.x < SS) g_bar[threadIdx.x] = 0;
}

// ---------------- kernel 4: logits = hs @ W_out + b_out  (fp16 wmma, pipelined) ----------------
// CTA 128x128, BK=32, 8 warps, warp tile 32x64, 2 CTAs/SM.
// Bias pre-loaded into accumulators from g_bias16; direct fragment->gmem stores.
// Grid: x = m-tile (fastest, 16), y = n-tile (250) -> co-resident CTAs share W_out tiles in L2.
#define LG_ALD 40     // 32 + 8 pad (halfs)
#define LG_BLD 136    // 128 + 8 pad (halfs)

__global__ __launch_bounds__(256, 2) void logits_kernel(
    const float* __restrict__ Wout,
    float* __restrict__ out)
{
    __shared__ __half As[2][128 * LG_ALD];
    __shared__ __half Bs[2][32 * LG_BLD];

    const int tid  = threadIdx.x;
    const int wid  = tid >> 5;
    const int wm = wid & 3;             // m quarter (32 rows)
    const int wn = wid >> 2;            // n half (64 cols)
    const int m0 = blockIdx.x * 128;
    const int n0 = blockIdx.y * 128;

    // accumulators start at bias
    wmma::fragment<wmma::accumulator, 16, 16, 16, float> acc[2][4];
#pragma unroll
    for (int i = 0; i < 2; i++)
#pragma unroll
        for (int j = 0; j < 4; j++)
            wmma::load_matrix_sync(acc[i][j], g_bias16 + n0 + wn * 64 + j * 16,
                                   VOCAB, wmma::mem_row_major);

    // A: row = tid>>1, colbase = (tid&1)*16 -> 4x float4
    const int arow = tid >> 1;
    const int acb  = (tid & 1) * 16;
    const float* aptr = g_hs + (size_t)(m0 + arow) * HIDDEN + acb;
    // B: row = tid>>3, colbase = (tid&7)*4 -> 4x float4 at +i*32
    const int brow = tid >> 3;
    const int bcb  = (tid & 7) * 4;
    const float* bptr = Wout + (size_t)brow * VOCAB + n0 + bcb;

    float4 ra[4], rb[4];

    auto ldg_chunk = [&](int k0) {
#pragma unroll
        for (int i = 0; i < 4; i++) ra[i] = *(const float4*)(aptr + k0 + i * 4);
        const float* src = bptr + (size_t)k0 * VOCAB;
#pragma unroll
        for (int i = 0; i < 4; i++) rb[i] = *(const float4*)(src + i * 32);
    };
    auto sts_chunk = [&](int buf) {
        __half* da = &As[buf][arow * LG_ALD + acb];
#pragma unroll
        for (int i = 0; i < 4; i++) {
            *(__half2*)(da + i * 4)     = __floats2half2_rn(ra[i].x, ra[i].y);
            *(__half2*)(da + i * 4 + 2) = __floats2half2_rn(ra[i].z, ra[i].w);
        }
        __half* db = &Bs[buf][brow * LG_BLD + bcb];
#pragma unroll
        for (int i = 0; i < 4; i++) {
            *(__half2*)(db + i * 32)     = __floats2half2_rn(rb[i].x, rb[i].y);
            *(__half2*)(db + i * 32 + 2) = __floats2half2_rn(rb[i].z, rb[i].w);
        }
    };

    ldg_chunk(0);
    sts_chunk(0);
    __syncthreads();

    int buf = 0;
#pragma unroll 1
    for (int kc = 0; kc < 16; kc++) {
        if (kc < 15) ldg_chunk((kc + 1) * 32);        // LDG overlaps mmas below
#pragma unroll
        for (int ks = 0; ks < 2; ks++) {
            wmma::fragment<wmma::matrix_a, 16, 16, 16, __half, wmma::row_major> af[2];
            wmma::fragment<wmma::matrix_b, 16, 16, 16, __half, wmma::row_major> bf[4];
#pragma unroll
            for (int i = 0; i < 2; i++)
                wmma::load_matrix_sync(af[i], &As[buf][(wm * 32 + i * 16) * LG_ALD + ks * 16], LG_ALD);
#pragma unroll
            for (int j = 0; j < 4; j++)
                wmma::load_matrix_sync(bf[j], &Bs[buf][(ks * 16) * LG_BLD + wn * 64 + j * 16], LG_BLD);
#pragma unroll
            for (int i = 0; i < 2; i++)
#pragma unroll
                for (int j = 0; j < 4; j++)
                    wmma::mma_sync(acc[i][j], af[i], bf[j], acc[i][j]);
        }
        if (kc < 15) sts_chunk(buf ^ 1);
        __syncthreads();
        buf ^= 1;
    }

    // epilogue: direct fragment stores (bias already in acc)
#pragma unroll
    for (int i = 0; i < 2; i++) {
#pragma unroll
        for (int j = 0; j < 4; j++) {
            const int gm = m0 + wm * 32 + i * 16;
            const int gn = n0 + wn * 64 + j * 16;
            wmma::store_matrix_sync(out + (size_t)gm * VOCAB + gn, acc[i][j],
                                    VOCAB, wmma::mem_row_major);
        }
    }
}

// ---------------- launch ----------------
extern "C" void kernel_launch(void* const* d_in, const int* in_sizes, int n_in,
                              void* d_out, int out_size)
{
    const int*   tokens  = (const int*)  d_in[0];
    const float* context = (const float*)d_in[1];
    const float* emb     = (const float*)d_in[2];
    const float* W_ih    = (const float*)d_in[3];
    const float* b_ih    = (const float*)d_in[4];
    const float* W_ic    = (const float*)d_in[5];
    const float* b_ic    = (const float*)d_in[6];
    const float* W_x     = (const float*)d_in[7];
    const float* W_h     = (const float*)d_in[8];
    const float* b_g     = (const float*)d_in[9];
    const float* W_out   = (const float*)d_in[10];
    const float* b_out   = (const float*)d_in[11];
    float* out = (float*)d_out;

    cudaFuncSetAttribute(lstm_persist_kernel,
                         cudaFuncAttributeMaxDynamicSharedMemorySize, LSTM_SMEM);

    // order: profiled launch (index 3) = lstm_persist_kernel
    init_gemm_kernel<<<16, 128>>>(context, W_ih, b_ih, W_ic, b_ic);
    xg_kernel<<<dim3(16, 16), 256>>>(tokens, emb, W_x, b_g);
    bias_rep_kernel<<<(16 * VOCAB + 255) / 256, 256>>>(b_out);
    lstm_persist_kernel<<<NCTA, 256, LSTM_SMEM>>>(W_h, tokens);
    logits_kernel<<<dim3(16, 250), 256>>>(W_out, out);
    bar_reset_kernel<<<1, 64>>>();
}

// round 13
// speedup vs baseline: 2.5867x; 1.0675x over previous
#include <cuda_runtime.h>
#include <cuda_bf16.h>
#include <cuda_fp16.h>
#include <cstdint>
#include <mma.h>

using namespace nvcuda;

#define VOCAB  32000
#define EMBED  512
#define HIDDEN 512
#define CTXD   2048
#define BB     32
#define SS     64
#define MTOT   (BB * SS)      // 2048
#define GATES  (4 * HIDDEN)   // 2048
#define NCTA   128
#define HSTEP  (HIDDEN * BB)  // 16384 floats = 64KB per step

// ---------------- scratch (device globals; no allocation allowed) ----------------
__device__ float g_xg[MTOT * GATES];                    // 16 MB
__device__ float g_hs[MTOT * HIDDEN];                   // 4 MB : [m][k] for logits
__device__ __align__(128) float g_hseq[SS * HSTEP];     // 4 MB : [t][k][b] for recurrence (bulk-copy src)
__device__ __align__(128) float g_h0T[HSTEP];           // [k][b]
__device__ float g_c [BB * HIDDEN];
__device__ float g_bias16[16 * VOCAB];                  // 2 MB : b_out replicated over 16 rows
__device__ unsigned g_bar[SS];

// ---------------- kernel 0: replicate b_out into 16 rows ----------------
__global__ void bias_rep_kernel(const float* __restrict__ bout) {
    const int idx = blockIdx.x * 256 + threadIdx.x;
    if (idx < 16 * VOCAB) g_bias16[idx] = bout[idx % VOCAB];
}

// ---------------- kernel 1: [h0|c0] = tanh(ctx @ [W_ih|W_ic] + bias)  (tf32 wmma) ----------------
__global__ __launch_bounds__(128) void init_gemm_kernel(
    const float* __restrict__ context,
    const float* __restrict__ W_ih, const float* __restrict__ b_ih,
    const float* __restrict__ W_ic, const float* __restrict__ b_ic)
{
    __shared__ float Asm[32 * 68];
    __shared__ float Bsm[64 * 68];

    const int tid = threadIdx.x;
    const int wid = tid >> 5;
    const int lane = tid & 31;
    const int n0 = blockIdx.x * 64;
    const bool which = (n0 >= 512);
    const int ncol = n0 & 511;
    const float* W  = which ? W_ic : W_ih;
    const float* bv = which ? b_ic : b_ih;

    wmma::fragment<wmma::accumulator, 16, 16, 8, float> acc0, acc1;
    wmma::fill_fragment(acc0, 0.f);
    wmma::fill_fragment(acc1, 0.f);

    for (int kc = 0; kc < 32; kc++) {
        const int k0 = kc * 64;
        {
            const int row = tid >> 2;
            const int cb  = (tid & 3) * 16;
            const float* src = context + (size_t)row * CTXD + k0 + cb;
            float* dst = Asm + row * 68 + cb;
#pragma unroll
            for (int i = 0; i < 4; i++) {
                float4 v = *(const float4*)(src + i * 4);
                dst[i * 4 + 0] = wmma::__float_to_tf32(v.x);
                dst[i * 4 + 1] = wmma::__float_to_tf32(v.y);
                dst[i * 4 + 2] = wmma::__float_to_tf32(v.z);
                dst[i * 4 + 3] = wmma::__float_to_tf32(v.w);
            }
        }
        {
            const int r  = tid >> 1;
            const int c0 = (tid & 1) * 4;
            const float* src = W + (size_t)(k0 + r) * HIDDEN + ncol + c0;
            float* dst = Bsm + r * 68 + c0;
#pragma unroll
            for (int i = 0; i < 8; i++) {
                float4 v = *(const float4*)(src + i * 8);
                dst[i * 8 + 0] = wmma::__float_to_tf32(v.x);
                dst[i * 8 + 1] = wmma::__float_to_tf32(v.y);
                dst[i * 8 + 2] = wmma::__float_to_tf32(v.z);
                dst[i * 8 + 3] = wmma::__float_to_tf32(v.w);
            }
        }
        __syncthreads();
#pragma unroll
        for (int ks = 0; ks < 8; ks++) {
            wmma::fragment<wmma::matrix_a, 16, 16, 8, wmma::precision::tf32, wmma::row_major> a0, a1;
            wmma::fragment<wmma::matrix_b, 16, 16, 8, wmma::precision::tf32, wmma::row_major> bf;
            wmma::load_matrix_sync(a0, &Asm[ks * 8], 68);
            wmma::load_matrix_sync(a1, &Asm[16 * 68 + ks * 8], 68);
            wmma::load_matrix_sync(bf, &Bsm[(ks * 8) * 68 + wid * 16], 68);
            wmma::mma_sync(acc0, a0, bf, acc0);
            wmma::mma_sync(acc1, a1, bf, acc1);
        }
        __syncthreads();
    }

    float* stage = Asm + wid * 640;
    wmma::store_matrix_sync(stage, acc0, 20, wmma::mem_row_major);
    wmma::store_matrix_sync(stage + 16 * 20, acc1, 20, wmma::mem_row_major);
    __syncwarp();
#pragma unroll
    for (int p = 0; p < 16; p++) {
        const int e = p * 32 + lane;
        const int r = e >> 4, c = e & 15;     // r = batch
        const int j = ncol + wid * 16 + c;
        const float v = tanhf(stage[r * 20 + c] + bv[j]);
        if (which) g_c  [r * HIDDEN + j] = v;
        else       g_h0T[j * BB + r]     = wmma::__float_to_tf32(v);
    }
}

// ---------------- kernel 2: xg = gather(emb)@W_x + b  (tf32 wmma) ----------------
__global__ __launch_bounds__(256) void xg_kernel(
    const int*   __restrict__ tokens,
    const float* __restrict__ emb,
    const float* __restrict__ Wx,
    const float* __restrict__ bias)
{
    __shared__ float As[2][128 * 20];
    __shared__ float Bs[2][16 * 132];

    const int tid = threadIdx.x;
    const int wid = tid >> 5;
    const int lane = tid & 31;
    const int wm = wid >> 2;
    const int wn = wid & 3;
    const int m0 = blockIdx.y * 128, n0 = blockIdx.x * 128;

    const int arow = tid >> 1;
    const int acol = (tid & 1) * 8;
    const int tok  = tokens[m0 + arow];
    const float* aptr = emb + (size_t)tok * EMBED + acol;
    const int brow = tid >> 4;
    const int bcol = (tid & 15) * 4;
    const float* bptr = Wx + (size_t)brow * GATES + n0 + bcol;

    wmma::fragment<wmma::accumulator, 16, 16, 8, float> acc[4][2];
#pragma unroll
    for (int i = 0; i < 4; i++)
#pragma unroll
        for (int j = 0; j < 2; j++) wmma::fill_fragment(acc[i][j], 0.f);

    auto load_chunk = [&](int buf, int k0) {
        {
            float* dst = &As[buf][arow * 20 + acol];
            float4 v0 = *(const float4*)(aptr + k0);
            float4 v1 = *(const float4*)(aptr + k0 + 4);
            dst[0] = wmma::__float_to_tf32(v0.x); dst[1] = wmma::__float_to_tf32(v0.y);
            dst[2] = wmma::__float_to_tf32(v0.z); dst[3] = wmma::__float_to_tf32(v0.w);
            dst[4] = wmma::__float_to_tf32(v1.x); dst[5] = wmma::__float_to_tf32(v1.y);
            dst[6] = wmma::__float_to_tf32(v1.z); dst[7] = wmma::__float_to_tf32(v1.w);
        }
        {
            float* dst = &Bs[buf][brow * 132 + bcol];
#pragma unroll
            for (int i = 0; i < 2; i++) {
                float4 v = *(const float4*)(bptr + (size_t)k0 * GATES + i * 64);
                dst[i * 64 + 0] = wmma::__float_to_tf32(v.x);
                dst[i * 64 + 1] = wmma::__float_to_tf32(v.y);
                dst[i * 64 + 2] = wmma::__float_to_tf32(v.z);
                dst[i * 64 + 3] = wmma::__float_to_tf32(v.w);
            }
        }
    };

    load_chunk(0, 0);
    __syncthreads();

    int buf = 0;
    for (int kc = 0; kc < 32; kc++) {
        if (kc < 31) load_chunk(buf ^ 1, (kc + 1) * 16);
#pragma unroll
        for (int ks = 0; ks < 2; ks++) {
            wmma::fragment<wmma::matrix_a, 16, 16, 8, wmma::precision::tf32, wmma::row_major> af[4];
            wmma::fragment<wmma::matrix_b, 16, 16, 8, wmma::precision::tf32, wmma::row_major> bf[2];
#pragma unroll
            for (int i = 0; i < 4; i++)
                wmma::load_matrix_sync(af[i], &As[buf][(wm * 64 + i * 16) * 20 + ks * 8], 20);
#pragma unroll
            for (int j = 0; j < 2; j++)
                wmma::load_matrix_sync(bf[j], &Bs[buf][(ks * 8) * 132 + wn * 32 + j * 16], 132);
#pragma unroll
            for (int i = 0; i < 4; i++)
#pragma unroll
                for (int j = 0; j < 2; j++)
                    wmma::mma_sync(acc[i][j], af[i], bf[j], acc[i][j]);
        }
        __syncthreads();
        buf ^= 1;
    }

    float* stage = ((float*)As) + wid * 320;
#pragma unroll
    for (int i = 0; i < 4; i++) {
#pragma unroll
        for (int j = 0; j < 2; j++) {
            wmma::store_matrix_sync(stage, acc[i][j], 20, wmma::mem_row_major);
            __syncwarp();
#pragma unroll
            for (int p = 0; p < 8; p++) {
                const int e = p * 32 + lane;
                const int row = e >> 4, col = e & 15;
                const int gm = m0 + wm * 64 + i * 16 + row;
                const int gn = n0 + wn * 32 + j * 16 + col;
                g_xg[(size_t)gm * GATES + gn] = stage[row * 20 + col] + __ldg(&bias[gn]);
            }
            __syncwarp();
        }
    }
}

// ---------------- kernel 3: persistent LSTM with cp.async.bulk h-broadcast ----------------
// h stored [t][k][b] contiguous 64KB per step -> one UBLKCP per CTA per step.
// smem hsm [k][b] consumed as col_major wmma A fragments (ldm=32).
#define HSMF   (HIDDEN * BB)             // 16384 floats = 64KB
#define WSMF   (512 * 16)                // 8192
#define REDF   (8 * 512)                 // 4096
#define LSTM_SMEM ((HSMF + WSMF + REDF + 512 + 128) * 4 + MTOT * 4)

__global__ __launch_bounds__(256) void lstm_persist_kernel(
    const float* __restrict__ Wh,
    const int*   __restrict__ tokens)
{
    extern __shared__ float sm[];
    float* hsm  = sm;                     // [k][b] 512 x 32
    float* wsm  = sm + HSMF;              // [k][c] 512 x 16
    float* red  = wsm + WSMF;             // [w][b*16+c] 8 x 512
    float* rsum = red + REDF;             // [512]
    float* csm  = rsum + 512;             // [128]
    int*   tsm  = (int*)(csm + 128);      // [2048]
    __shared__ alignas(8) unsigned long long mbar_sto;

    const int tid  = threadIdx.x;
    const int wid  = tid >> 5;
    const int jbase = blockIdx.x * 4;

    // smem u32 addresses for PTX
    unsigned int hsm_addr, mbar_addr;
    asm("{ .reg .u64 t; cvta.to.shared.u64 t, %1; cvt.u32.u64 %0, t; }"
        : "=r"(hsm_addr) : "l"(hsm));
    asm("{ .reg .u64 t; cvta.to.shared.u64 t, %1; cvt.u32.u64 %0, t; }"
        : "=r"(mbar_addr) : "l"(&mbar_sto));

    // one-time: W_h slice, c0, tokens, mbarrier init
    for (int idx = tid; idx < WSMF; idx += 256) {
        const int k = idx >> 4, c = idx & 15;
        wsm[idx] = wmma::__float_to_tf32(
            Wh[(size_t)k * GATES + ((c >> 2) << 9) + jbase + (c & 3)]);
    }
    if (tid < 128) {
        const int b = tid & 31, jl = tid >> 5;
        csm[tid] = g_c[b * HIDDEN + jbase + jl];
    }
    for (int idx = tid; idx < MTOT; idx += 256) tsm[idx] = tokens[idx];
    if (tid == 0)
        asm volatile("mbarrier.init.shared.b64 [%0], 1;" :: "r"(mbar_addr) : "memory");
    __syncthreads();

    // preload B fragments (register-resident for whole kernel)
    wmma::fragment<wmma::matrix_b, 16, 16, 8, wmma::precision::tf32, wmma::row_major> bk[8];
#pragma unroll
    for (int ks = 0; ks < 8; ks++)
        wmma::load_matrix_sync(bk[ks], &wsm[(wid * 64 + ks * 8) * 16], 16);
    __syncthreads();

    for (int t = 0; t < SS; t++) {
        // ---- issue bulk copy of h_{t-1} (64KB, single UBLKCP) ----
        if (tid == 0) {
            const float* src = (t == 0) ? g_h0T : (g_hseq + (size_t)(t - 1) * HSTEP);
            asm volatile("mbarrier.arrive.expect_tx.shared.b64 _, [%0], %1;"
                         :: "r"(mbar_addr), "r"(65536u) : "memory");
            asm volatile("cp.async.bulk.shared::cta.global.mbarrier::complete_tx::bytes "
                         "[%0], [%1], %2, [%3];"
                         :: "r"(hsm_addr), "l"(src), "r"(65536u), "r"(mbar_addr) : "memory");
        }

        // ---- prefetch xg (overlaps copy) ----
        float x0 = 0.f, x1 = 0.f, x2 = 0.f, x3 = 0.f;
        int b_f = 0, jl_f = 0, m_f = 0;
        if (tid < 128) {
            b_f = tid & 31; jl_f = tid >> 5;
            m_f = (b_f << 6) + t;
            const size_t xb = (size_t)m_f * GATES + jbase + jl_f;
            x0 = g_xg[xb];
            x1 = g_xg[xb + 512];
            x2 = g_xg[xb + 1024];
            x3 = g_xg[xb + 1536];
        }

        // ---- wait for copy completion (phase parity = t&1) ----
        {
            const unsigned parity = (unsigned)(t & 1);
            unsigned done;
            do {
                asm volatile(
                    "{ .reg .pred p;\n\t"
                    "mbarrier.try_wait.parity.acquire.cta.shared::cta.b64 p, [%1], %2, 0x989680;\n\t"
                    "selp.b32 %0, 1, 0, p; }"
                    : "=r"(done) : "r"(mbar_addr), "r"(parity) : "memory");
            } while (!done);
        }

        // ---- wmma: col_major A from [k][b] smem ----
        wmma::fragment<wmma::accumulator, 16, 16, 8, float> acc0, acc1;
        wmma::fill_fragment(acc0, 0.f);
        wmma::fill_fragment(acc1, 0.f);
#pragma unroll
        for (int ks = 0; ks < 8; ks++) {
            const int k0 = wid * 64 + ks * 8;
            wmma::fragment<wmma::matrix_a, 16, 16, 8, wmma::precision::tf32, wmma::col_major> a0, a1;
            wmma::load_matrix_sync(a0, &hsm[k0 * BB],      BB);   // batches 0..15
            wmma::load_matrix_sync(a1, &hsm[k0 * BB + 16], BB);   // batches 16..31
            wmma::mma_sync(acc0, a0, bk[ks], acc0);
            wmma::mma_sync(acc1, a1, bk[ks], acc1);
        }
        wmma::store_matrix_sync(&red[wid * 512],       acc0, 16, wmma::mem_row_major);
        wmma::store_matrix_sync(&red[wid * 512 + 256], acc1, 16, wmma::mem_row_major);
        __syncthreads();

        // ---- reduce 8 warp partials ----
        {
            float s0 = 0.f, s1 = 0.f;
            const int o = tid;
#pragma unroll
            for (int w = 0; w < 8; w++) {
                s0 += red[w * 512 + o];
                s1 += red[w * 512 + o + 256];
            }
            rsum[o] = s0; rsum[o + 256] = s1;
        }
        __syncthreads();

        // ---- finalize ----
        if (tid < 128) {
            const int b = b_f, jl = jl_f, m = m_f;
            const int j = jbase + jl;
            const float zi = x0 + rsum[b * 16 +  0 + jl];
            const float zf = x1 + rsum[b * 16 +  4 + jl];
            const float zg = x2 + rsum[b * 16 +  8 + jl];
            const float zo = x3 + rsum[b * 16 + 12 + jl];
            const float c_old = csm[tid];
            const float si = 1.f / (1.f + expf(-zi));
            const float sf = 1.f / (1.f + expf(-zf));
            const float so = 1.f / (1.f + expf(-zo));
            const float cn = sf * c_old + si * tanhf(zg);
            const float hn = so * tanhf(cn);
            const bool msk = (tsm[m] != 0);
            const float ho = msk ? wmma::__float_to_tf32(hn) : hsm[j * BB + b];
            const float co = msk ? cn : c_old;
            csm[tid] = co;
            g_hs[(size_t)m * HIDDEN + j] = ho;                    // [m][k] for logits
            g_hseq[(size_t)t * HSTEP + j * BB + b] = ho;          // [t][k][b] for recurrence
        }

        // ---- grid barrier ----
        if (t < SS - 1) {
            __threadfence();
            __syncthreads();
            if (tid == 0) {
                atomicAdd(&g_bar[t], 1u);
                while (((volatile unsigned*)g_bar)[t] < (unsigned)NCTA)
                    __nanosleep(64);
                __threadfence();
            }
            __syncthreads();
        }
    }
}

__global__ void bar_reset_kernel() {
    if (threadIdx.x < SS) g_bar[threadIdx.x] = 0;
}

// ---------------- kernel 4: logits = hs @ W_out + b_out  (fp16 wmma, pipelined) ----------------
#define LG_ALD 40
#define LG_BLD 136

__global__ __launch_bounds__(256, 2) void logits_kernel(
    const float* __restrict__ Wout,
    float* __restrict__ out)
{
    __shared__ __half As[2][128 * LG_ALD];
    __shared__ __half Bs[2][32 * LG_BLD];

    const int tid  = threadIdx.x;
    const int wid  = tid >> 5;
    const int wm = wid & 3;
    const int wn = wid >> 2;
    const int m0 = blockIdx.x * 128;
    const int n0 = blockIdx.y * 128;

    wmma::fragment<wmma::accumulator, 16, 16, 16, float> acc[2][4];
#pragma unroll
    for (int i = 0; i < 2; i++)
#pragma unroll
        for (int j = 0; j < 4; j++)
            wmma::load_matrix_sync(acc[i][j], g_bias16 + n0 + wn * 64 + j * 16,
                                   VOCAB, wmma::mem_row_major);

    const int arow = tid >> 1;
    const int acb  = (tid & 1) * 16;
    const float* aptr = g_hs + (size_t)(m0 + arow) * HIDDEN + acb;
    const int brow = tid >> 3;
    const int bcb  = (tid & 7) * 4;
    const float* bptr = Wout + (size_t)brow * VOCAB + n0 + bcb;

    float4 ra[4], rb[4];

    auto ldg_chunk = [&](int k0) {
#pragma unroll
        for (int i = 0; i < 4; i++) ra[i] = *(const float4*)(aptr + k0 + i * 4);
        const float* src = bptr + (size_t)k0 * VOCAB;
#pragma unroll
        for (int i = 0; i < 4; i++) rb[i] = *(const float4*)(src + i * 32);
    };
    auto sts_chunk = [&](int buf) {
        __half* da = &As[buf][arow * LG_ALD + acb];
#pragma unroll
        for (int i = 0; i < 4; i++) {
            *(__half2*)(da + i * 4)     = __floats2half2_rn(ra[i].x, ra[i].y);
            *(__half2*)(da + i * 4 + 2) = __floats2half2_rn(ra[i].z, ra[i].w);
        }
        __half* db = &Bs[buf][brow * LG_BLD + bcb];
#pragma unroll
        for (int i = 0; i < 4; i++) {
            *(__half2*)(db + i * 32)     = __floats2half2_rn(rb[i].x, rb[i].y);
            *(__half2*)(db + i * 32 + 2) = __floats2half2_rn(rb[i].z, rb[i].w);
        }
    };

    ldg_chunk(0);
    sts_chunk(0);
    __syncthreads();

    int buf = 0;
#pragma unroll 1
    for (int kc = 0; kc < 16; kc++) {
        if (kc < 15) ldg_chunk((kc + 1) * 32);
#pragma unroll
        for (int ks = 0; ks < 2; ks++) {
            wmma::fragment<wmma::matrix_a, 16, 16, 16, __half, wmma::row_major> af[2];
            wmma::fragment<wmma::matrix_b, 16, 16, 16, __half, wmma::row_major> bf[4];
#pragma unroll
            for (int i = 0; i < 2; i++)
                wmma::load_matrix_sync(af[i], &As[buf][(wm * 32 + i * 16) * LG_ALD + ks * 16], LG_ALD);
#pragma unroll
            for (int j = 0; j < 4; j++)
                wmma::load_matrix_sync(bf[j], &Bs[buf][(ks * 16) * LG_BLD + wn * 64 + j * 16], LG_BLD);
#pragma unroll
            for (int i = 0; i < 2; i++)
#pragma unroll
                for (int j = 0; j < 4; j++)
                    wmma::mma_sync(acc[i][j], af[i], bf[j], acc[i][j]);
        }
        if (kc < 15) sts_chunk(buf ^ 1);
        __syncthreads();
        buf ^= 1;
    }

#pragma unroll
    for (int i = 0; i < 2; i++) {
#pragma unroll
        for (int j = 0; j < 4; j++) {
            const int gm = m0 + wm * 32 + i * 16;
            const int gn = n0 + wn * 64 + j * 16;
            wmma::store_matrix_sync(out + (size_t)gm * VOCAB + gn, acc[i][j],
                                    VOCAB, wmma::mem_row_major);
        }
    }
}

// ---------------- launch ----------------
extern "C" void kernel_launch(void* const* d_in, const int* in_sizes, int n_in,
                              void* d_out, int out_size)
{
    const int*   tokens  = (const int*)  d_in[0];
    const float* context = (const float*)d_in[1];
    const float* emb     = (const float*)d_in[2];
    const float* W_ih    = (const float*)d_in[3];
    const float* b_ih    = (const float*)d_in[4];
    const float* W_ic    = (const float*)d_in[5];
    const float* b_ic    = (const float*)d_in[6];
    const float* W_x     = (const float*)d_in[7];
    const float* W_h     = (const float*)d_in[8];
    const float* b_g     = (const float*)d_in[9];
    const float* W_out   = (const float*)d_in[10];
    const float* b_out   = (const float*)d_in[11];
    float* out = (float*)d_out;

    cudaFuncSetAttribute(lstm_persist_kernel,
                         cudaFuncAttributeMaxDynamicSharedMemorySize, LSTM_SMEM);

    // order: profiled launch (index 3) = lstm_persist_kernel
    init_gemm_kernel<<<16, 128>>>(context, W_ih, b_ih, W_ic, b_ic);
    xg_kernel<<<dim3(16, 16), 256>>>(tokens, emb, W_x, b_g);
    bias_rep_kernel<<<(16 * VOCAB + 255) / 256, 256>>>(b_out);
    lstm_persist_kernel<<<NCTA, 256, LSTM_SMEM>>>(W_h, tokens);
    logits_kernel<<<dim3(16, 250), 256>>>(W_out, out);
    bar_reset_kernel<<<1, 64>>>();
}

// round 14
// speedup vs baseline: 2.6891x; 1.0396x over previous
#include <cuda_runtime.h>
#include <cuda_bf16.h>
#include <cuda_fp16.h>
#include <cstdint>
#include <mma.h>

using namespace nvcuda;

#define VOCAB  32000
#define EMBED  512
#define HIDDEN 512
#define CTXD   2048
#define BB     32
#define SS     64
#define MTOT   (BB * SS)      // 2048
#define GATES  (4 * HIDDEN)   // 2048
#define NCTA   128
#define HSTEP  (HIDDEN * BB)  // 16384 floats = 64KB per step

// ---------------- scratch (device globals; no allocation allowed) ----------------
__device__ float  g_xg[MTOT * GATES];                   // 16 MB
__device__ __half g_hs_h[MTOT * HIDDEN];                // 2 MB : [m][k] fp16 for logits
__device__ __align__(128) float g_hseq[SS * HSTEP];     // 4 MB : [t][k][b] (bulk-copy src)
__device__ __align__(128) float g_h0T[HSTEP];           // [k][b]
__device__ float  g_c [BB * HIDDEN];
__device__ float  g_bias16[16 * VOCAB];                 // 2 MB : b_out replicated
__device__ __align__(128) __half g_wout_h[(size_t)VOCAB * HIDDEN];  // 33 MB fp16 W_out
__device__ unsigned g_bar[SS];

__device__ __forceinline__ unsigned smem_u32(const void* p) {
    return (unsigned)__cvta_generic_to_shared(p);
}
#define CPA16(d, s) asm volatile("cp.async.cg.shared.global [%0], [%1], 16;" :: "r"(d), "l"(s))

// ---------------- kernel prep: W_out->fp16, bias replicate, bar reset ----------------
__global__ __launch_bounds__(256) void prep_kernel(
    const float* __restrict__ Wout, const float* __restrict__ bout)
{
    const int tid = threadIdx.x;
    const int bx  = blockIdx.x;
    if (bx < 128) {
        const size_t base = (size_t)bx * 128000;        // 128 blocks x 128000 = 16.384M
        for (int i = tid; i < 32000; i += 256) {
            const size_t off = base + (size_t)i * 4;
            float4 v = *(const float4*)(Wout + off);
            __half2* dst = (__half2*)(g_wout_h + off);
            dst[0] = __floats2half2_rn(v.x, v.y);
            dst[1] = __floats2half2_rn(v.z, v.w);
        }
    } else {
        const int r = bx - 128;                         // 0..15
        for (int i = tid; i < VOCAB; i += 256)
            g_bias16[r * VOCAB + i] = bout[i];
        if (r == 0 && tid < SS) g_bar[tid] = 0;
    }
}

// ---------------- kernel 1: [h0|c0] = tanh(ctx @ [W_ih|W_ic] + bias)  (tf32 wmma) ----------------
__global__ __launch_bounds__(128) void init_gemm_kernel(
    const float* __restrict__ context,
    const float* __restrict__ W_ih, const float* __restrict__ b_ih,
    const float* __restrict__ W_ic, const float* __restrict__ b_ic)
{
    __shared__ float Asm[32 * 68];
    __shared__ float Bsm[64 * 68];

    const int tid = threadIdx.x;
    const int wid = tid >> 5;
    const int lane = tid & 31;
    const int n0 = blockIdx.x * 64;
    const bool which = (n0 >= 512);
    const int ncol = n0 & 511;
    const float* W  = which ? W_ic : W_ih;
    const float* bv = which ? b_ic : b_ih;

    wmma::fragment<wmma::accumulator, 16, 16, 8, float> acc0, acc1;
    wmma::fill_fragment(acc0, 0.f);
    wmma::fill_fragment(acc1, 0.f);

    for (int kc = 0; kc < 32; kc++) {
        const int k0 = kc * 64;
        {
            const int row = tid >> 2;
            const int cb  = (tid & 3) * 16;
            const float* src = context + (size_t)row * CTXD + k0 + cb;
            float* dst = Asm + row * 68 + cb;
#pragma unroll
            for (int i = 0; i < 4; i++) {
                float4 v = *(const float4*)(src + i * 4);
                dst[i * 4 + 0] = wmma::__float_to_tf32(v.x);
                dst[i * 4 + 1] = wmma::__float_to_tf32(v.y);
                dst[i * 4 + 2] = wmma::__float_to_tf32(v.z);
                dst[i * 4 + 3] = wmma::__float_to_tf32(v.w);
            }
        }
        {
            const int r  = tid >> 1;
            const int c0 = (tid & 1) * 4;
            const float* src = W + (size_t)(k0 + r) * HIDDEN + ncol + c0;
            float* dst = Bsm + r * 68 + c0;
#pragma unroll
            for (int i = 0; i < 8; i++) {
                float4 v = *(const float4*)(src + i * 8);
                dst[i * 8 + 0] = wmma::__float_to_tf32(v.x);
                dst[i * 8 + 1] = wmma::__float_to_tf32(v.y);
                dst[i * 8 + 2] = wmma::__float_to_tf32(v.z);
                dst[i * 8 + 3] = wmma::__float_to_tf32(v.w);
            }
        }
        __syncthreads();
#pragma unroll
        for (int ks = 0; ks < 8; ks++) {
            wmma::fragment<wmma::matrix_a, 16, 16, 8, wmma::precision::tf32, wmma::row_major> a0, a1;
            wmma::fragment<wmma::matrix_b, 16, 16, 8, wmma::precision::tf32, wmma::row_major> bf;
            wmma::load_matrix_sync(a0, &Asm[ks * 8], 68);
            wmma::load_matrix_sync(a1, &Asm[16 * 68 + ks * 8], 68);
            wmma::load_matrix_sync(bf, &Bsm[(ks * 8) * 68 + wid * 16], 68);
            wmma::mma_sync(acc0, a0, bf, acc0);
            wmma::mma_sync(acc1, a1, bf, acc1);
        }
        __syncthreads();
    }

    float* stage = Asm + wid * 640;
    wmma::store_matrix_sync(stage, acc0, 20, wmma::mem_row_major);
    wmma::store_matrix_sync(stage + 16 * 20, acc1, 20, wmma::mem_row_major);
    __syncwarp();
#pragma unroll
    for (int p = 0; p < 16; p++) {
        const int e = p * 32 + lane;
        const int r = e >> 4, c = e & 15;     // r = batch
        const int j = ncol + wid * 16 + c;
        const float v = tanhf(stage[r * 20 + c] + bv[j]);
        if (which) g_c  [r * HIDDEN + j] = v;
        else       g_h0T[j * BB + r]     = wmma::__float_to_tf32(v);
    }
}

// ---------------- kernel 2: xg = gather(emb)@W_x + b  (tf32 wmma) ----------------
__global__ __launch_bounds__(256) void xg_kernel(
    const int*   __restrict__ tokens,
    const float* __restrict__ emb,
    const float* __restrict__ Wx,
    const float* __restrict__ bias)
{
    __shared__ float As[2][128 * 20];
    __shared__ float Bs[2][16 * 132];

    const int tid = threadIdx.x;
    const int wid = tid >> 5;
    const int lane = tid & 31;
    const int wm = wid >> 2;
    const int wn = wid & 3;
    const int m0 = blockIdx.y * 128, n0 = blockIdx.x * 128;

    const int arow = tid >> 1;
    const int acol = (tid & 1) * 8;
    const int tok  = tokens[m0 + arow];
    const float* aptr = emb + (size_t)tok * EMBED + acol;
    const int brow = tid >> 4;
    const int bcol = (tid & 15) * 4;
    const float* bptr = Wx + (size_t)brow * GATES + n0 + bcol;

    wmma::fragment<wmma::accumulator, 16, 16, 8, float> acc[4][2];
#pragma unroll
    for (int i = 0; i < 4; i++)
#pragma unroll
        for (int j = 0; j < 2; j++) wmma::fill_fragment(acc[i][j], 0.f);

    auto load_chunk = [&](int buf, int k0) {
        {
            float* dst = &As[buf][arow * 20 + acol];
            float4 v0 = *(const float4*)(aptr + k0);
            float4 v1 = *(const float4*)(aptr + k0 + 4);
            dst[0] = wmma::__float_to_tf32(v0.x); dst[1] = wmma::__float_to_tf32(v0.y);
            dst[2] = wmma::__float_to_tf32(v0.z); dst[3] = wmma::__float_to_tf32(v0.w);
            dst[4] = wmma::__float_to_tf32(v1.x); dst[5] = wmma::__float_to_tf32(v1.y);
            dst[6] = wmma::__float_to_tf32(v1.z); dst[7] = wmma::__float_to_tf32(v1.w);
        }
        {
            float* dst = &Bs[buf][brow * 132 + bcol];
#pragma unroll
            for (int i = 0; i < 2; i++) {
                float4 v = *(const float4*)(bptr + (size_t)k0 * GATES + i * 64);
                dst[i * 64 + 0] = wmma::__float_to_tf32(v.x);
                dst[i * 64 + 1] = wmma::__float_to_tf32(v.y);
                dst[i * 64 + 2] = wmma::__float_to_tf32(v.z);
                dst[i * 64 + 3] = wmma::__float_to_tf32(v.w);
            }
        }
    };

    load_chunk(0, 0);
    __syncthreads();

    int buf = 0;
    for (int kc = 0; kc < 32; kc++) {
        if (kc < 31) load_chunk(buf ^ 1, (kc + 1) * 16);
#pragma unroll
        for (int ks = 0; ks < 2; ks++) {
            wmma::fragment<wmma::matrix_a, 16, 16, 8, wmma::precision::tf32, wmma::row_major> af[4];
            wmma::fragment<wmma::matrix_b, 16, 16, 8, wmma::precision::tf32, wmma::row_major> bf[2];
#pragma unroll
            for (int i = 0; i < 4; i++)
                wmma::load_matrix_sync(af[i], &As[buf][(wm * 64 + i * 16) * 20 + ks * 8], 20);
#pragma unroll
            for (int j = 0; j < 2; j++)
                wmma::load_matrix_sync(bf[j], &Bs[buf][(ks * 8) * 132 + wn * 32 + j * 16], 132);
#pragma unroll
            for (int i = 0; i < 4; i++)
#pragma unroll
                for (int j = 0; j < 2; j++)
                    wmma::mma_sync(acc[i][j], af[i], bf[j], acc[i][j]);
        }
        __syncthreads();
        buf ^= 1;
    }

    float* stage = ((float*)As) + wid * 320;
#pragma unroll
    for (int i = 0; i < 4; i++) {
#pragma unroll
        for (int j = 0; j < 2; j++) {
            wmma::store_matrix_sync(stage, acc[i][j], 20, wmma::mem_row_major);
            __syncwarp();
#pragma unroll
            for (int p = 0; p < 8; p++) {
                const int e = p * 32 + lane;
                const int row = e >> 4, col = e & 15;
                const int gm = m0 + wm * 64 + i * 16 + row;
                const int gn = n0 + wn * 32 + j * 16 + col;
                g_xg[(size_t)gm * GATES + gn] = stage[row * 20 + col] + __ldg(&bias[gn]);
            }
            __syncwarp();
        }
    }
}

// ---------------- kernel 3: persistent LSTM with cp.async.bulk h-broadcast ----------------
#define HSMF   (HIDDEN * BB)             // 16384 floats = 64KB
#define WSMF   (512 * 16)                // 8192
#define REDF   (8 * 512)                 // 4096
#define LSTM_SMEM ((HSMF + WSMF + REDF + 512 + 128) * 4 + MTOT * 4)

__global__ __launch_bounds__(256) void lstm_persist_kernel(
    const float* __restrict__ Wh,
    const int*   __restrict__ tokens)
{
    extern __shared__ float sm[];
    float* hsm  = sm;                     // [k][b] 512 x 32
    float* wsm  = sm + HSMF;              // [k][c] 512 x 16
    float* red  = wsm + WSMF;             // [w][b*16+c] 8 x 512
    float* rsum = red + REDF;             // [512]
    float* csm  = rsum + 512;             // [128]
    int*   tsm  = (int*)(csm + 128);      // [2048]
    __shared__ alignas(8) unsigned long long mbar_sto;

    const int tid  = threadIdx.x;
    const int wid  = tid >> 5;
    const int jbase = blockIdx.x * 4;

    unsigned int hsm_addr, mbar_addr;
    asm("{ .reg .u64 t; cvta.to.shared.u64 t, %1; cvt.u32.u64 %0, t; }"
        : "=r"(hsm_addr) : "l"(hsm));
    asm("{ .reg .u64 t; cvta.to.shared.u64 t, %1; cvt.u32.u64 %0, t; }"
        : "=r"(mbar_addr) : "l"(&mbar_sto));

    for (int idx = tid; idx < WSMF; idx += 256) {
        const int k = idx >> 4, c = idx & 15;
        wsm[idx] = wmma::__float_to_tf32(
            Wh[(size_t)k * GATES + ((c >> 2) << 9) + jbase + (c & 3)]);
    }
    if (tid < 128) {
        const int b = tid & 31, jl = tid >> 5;
        csm[tid] = g_c[b * HIDDEN + jbase + jl];
    }
    for (int idx = tid; idx < MTOT; idx += 256) tsm[idx] = tokens[idx];
    if (tid == 0)
        asm volatile("mbarrier.init.shared.b64 [%0], 1;" :: "r"(mbar_addr) : "memory");
    __syncthreads();

    wmma::fragment<wmma::matrix_b, 16, 16, 8, wmma::precision::tf32, wmma::row_major> bk[8];
#pragma unroll
    for (int ks = 0; ks < 8; ks++)
        wmma::load_matrix_sync(bk[ks], &wsm[(wid * 64 + ks * 8) * 16], 16);
    __syncthreads();

    for (int t = 0; t < SS; t++) {
        if (tid == 0) {
            const float* src = (t == 0) ? g_h0T : (g_hseq + (size_t)(t - 1) * HSTEP);
            asm volatile("mbarrier.arrive.expect_tx.shared.b64 _, [%0], %1;"
                         :: "r"(mbar_addr), "r"(65536u) : "memory");
            asm volatile("cp.async.bulk.shared::cta.global.mbarrier::complete_tx::bytes "
                         "[%0], [%1], %2, [%3];"
                         :: "r"(hsm_addr), "l"(src), "r"(65536u), "r"(mbar_addr) : "memory");
        }

        float x0 = 0.f, x1 = 0.f, x2 = 0.f, x3 = 0.f;
        int b_f = 0, jl_f = 0, m_f = 0;
        if (tid < 128) {
            b_f = tid & 31; jl_f = tid >> 5;
            m_f = (b_f << 6) + t;
            const size_t xb = (size_t)m_f * GATES + jbase + jl_f;
            x0 = g_xg[xb];
            x1 = g_xg[xb + 512];
            x2 = g_xg[xb + 1024];
            x3 = g_xg[xb + 1536];
        }

        {
            const unsigned parity = (unsigned)(t & 1);
            unsigned done;
            do {
                asm volatile(
                    "{ .reg .pred p;\n\t"
                    "mbarrier.try_wait.parity.acquire.cta.shared::cta.b64 p, [%1], %2, 0x989680;\n\t"
                    "selp.b32 %0, 1, 0, p; }"
                    : "=r"(done) : "r"(mbar_addr), "r"(parity) : "memory");
            } while (!done);
        }

        wmma::fragment<wmma::accumulator, 16, 16, 8, float> acc0, acc1;
        wmma::fill_fragment(acc0, 0.f);
        wmma::fill_fragment(acc1, 0.f);
#pragma unroll
        for (int ks = 0; ks < 8; ks++) {
            const int k0 = wid * 64 + ks * 8;
            wmma::fragment<wmma::matrix_a, 16, 16, 8, wmma::precision::tf32, wmma::col_major> a0, a1;
            wmma::load_matrix_sync(a0, &hsm[k0 * BB],      BB);
            wmma::load_matrix_sync(a1, &hsm[k0 * BB + 16], BB);
            wmma::mma_sync(acc0, a0, bk[ks], acc0);
            wmma::mma_sync(acc1, a1, bk[ks], acc1);
        }
        wmma::store_matrix_sync(&red[wid * 512],       acc0, 16, wmma::mem_row_major);
        wmma::store_matrix_sync(&red[wid * 512 + 256], acc1, 16, wmma::mem_row_major);
        __syncthreads();

        {
            float s0 = 0.f, s1 = 0.f;
            const int o = tid;
#pragma unroll
            for (int w = 0; w < 8; w++) {
                s0 += red[w * 512 + o];
                s1 += red[w * 512 + o + 256];
            }
            rsum[o] = s0; rsum[o + 256] = s1;
        }
        __syncthreads();

        if (tid < 128) {
            const int b = b_f, jl = jl_f, m = m_f;
            const int j = jbase + jl;
            const float zi = x0 + rsum[b * 16 +  0 + jl];
            const float zf = x1 + rsum[b * 16 +  4 + jl];
            const float zg = x2 + rsum[b * 16 +  8 + jl];
            const float zo = x3 + rsum[b * 16 + 12 + jl];
            const float c_old = csm[tid];
            const float si = 1.f / (1.f + expf(-zi));
            const float sf = 1.f / (1.f + expf(-zf));
            const float so = 1.f / (1.f + expf(-zo));
            const float cn = sf * c_old + si * tanhf(zg);
            const float hn = so * tanhf(cn);
            const bool msk = (tsm[m] != 0);
            const float ho = msk ? wmma::__float_to_tf32(hn) : hsm[j * BB + b];
            const float co = msk ? cn : c_old;
            csm[tid] = co;
            g_hs_h[(size_t)m * HIDDEN + j] = __float2half_rn(ho);
            g_hseq[(size_t)t * HSTEP + j * BB + b] = ho;
        }

        if (t < SS - 1) {
            __threadfence();
            __syncthreads();
            if (tid == 0) {
                atomicAdd(&g_bar[t], 1u);
                while (((volatile unsigned*)g_bar)[t] < (unsigned)NCTA)
                    __nanosleep(64);
                __threadfence();
            }
            __syncthreads();
        }
    }
}

// ---------------- kernel 4: logits = hs @ W_out + b_out  (fp16 wmma, cp.async pipeline) ----------------
#define LG_ALD 40
#define LG_BLD 136

__global__ __launch_bounds__(256, 2) void logits_kernel(float* __restrict__ out)
{
    __shared__ __half As[2][128 * LG_ALD];
    __shared__ __half Bs[2][32 * LG_BLD];

    const int tid = threadIdx.x;
    const int wid = tid >> 5;
    const int wm = wid & 3;
    const int wn = wid >> 2;
    const int m0 = blockIdx.x * 128;
    const int n0 = blockIdx.y * 128;

    wmma::fragment<wmma::accumulator, 16, 16, 16, float> acc[2][4];
#pragma unroll
    for (int i = 0; i < 2; i++)
#pragma unroll
        for (int j = 0; j < 4; j++)
            wmma::load_matrix_sync(acc[i][j], g_bias16 + n0 + wn * 64 + j * 16,
                                   VOCAB, wmma::mem_row_major);

    const int arow = tid >> 1;
    const int acb  = (tid & 1) * 16;
    const __half* aptr = g_hs_h + (size_t)(m0 + arow) * HIDDEN + acb;
    const int brow = tid >> 3;
    const int bcb  = (tid & 7) * 16;
    const __half* bptr = g_wout_h + (size_t)brow * VOCAB + n0 + bcb;

    const unsigned da0 = smem_u32(&As[0][arow * LG_ALD + acb]);
    const unsigned da1 = smem_u32(&As[1][arow * LG_ALD + acb]);
    const unsigned db0 = smem_u32(&Bs[0][brow * LG_BLD + bcb]);
    const unsigned db1 = smem_u32(&Bs[1][brow * LG_BLD + bcb]);

    auto issue = [&](int buf, int k0) {
        const unsigned da = buf ? da1 : da0;
        const unsigned db = buf ? db1 : db0;
        const __half* sa = aptr + k0;
        CPA16(da,      sa);
        CPA16(da + 16, sa + 8);
        const __half* sb = bptr + (size_t)k0 * VOCAB;
        CPA16(db,      sb);
        CPA16(db + 16, sb + 8);
        asm volatile("cp.async.commit_group;");
    };

    issue(0, 0);
    int buf = 0;
#pragma unroll 1
    for (int kc = 0; kc < 16; kc++) {
        if (kc < 15) {
            issue(buf ^ 1, (kc + 1) * 32);
            asm volatile("cp.async.wait_group 1;" ::: "memory");
        } else {
            asm volatile("cp.async.wait_group 0;" ::: "memory");
        }
        __syncthreads();
#pragma unroll
        for (int ks = 0; ks < 2; ks++) {
            wmma::fragment<wmma::matrix_a, 16, 16, 16, __half, wmma::row_major> af[2];
            wmma::fragment<wmma::matrix_b, 16, 16, 16, __half, wmma::row_major> bf[4];
#pragma unroll
            for (int i = 0; i < 2; i++)
                wmma::load_matrix_sync(af[i], &As[buf][(wm * 32 + i * 16) * LG_ALD + ks * 16], LG_ALD);
#pragma unroll
            for (int j = 0; j < 4; j++)
                wmma::load_matrix_sync(bf[j], &Bs[buf][(ks * 16) * LG_BLD + wn * 64 + j * 16], LG_BLD);
#pragma unroll
            for (int i = 0; i < 2; i++)
#pragma unroll
                for (int j = 0; j < 4; j++)
                    wmma::mma_sync(acc[i][j], af[i], bf[j], acc[i][j]);
        }
        __syncthreads();
        buf ^= 1;
    }

#pragma unroll
    for (int i = 0; i < 2; i++) {
#pragma unroll
        for (int j = 0; j < 4; j++) {
            const int gm = m0 + wm * 32 + i * 16;
            const int gn = n0 + wn * 64 + j * 16;
            wmma::store_matrix_sync(out + (size_t)gm * VOCAB + gn, acc[i][j],
                                    VOCAB, wmma::mem_row_major);
        }
    }
}

// ---------------- launch ----------------
extern "C" void kernel_launch(void* const* d_in, const int* in_sizes, int n_in,
                              void* d_out, int out_size)
{
    const int*   tokens  = (const int*)  d_in[0];
    const float* context = (const float*)d_in[1];
    const float* emb     = (const float*)d_in[2];
    const float* W_ih    = (const float*)d_in[3];
    const float* b_ih    = (const float*)d_in[4];
    const float* W_ic    = (const float*)d_in[5];
    const float* b_ic    = (const float*)d_in[6];
    const float* W_x     = (const float*)d_in[7];
    const float* W_h     = (const float*)d_in[8];
    const float* b_g     = (const float*)d_in[9];
    const float* W_out   = (const float*)d_in[10];
    const float* b_out   = (const float*)d_in[11];
    float* out = (float*)d_out;

    cudaFuncSetAttribute(lstm_persist_kernel,
                         cudaFuncAttributeMaxDynamicSharedMemorySize, LSTM_SMEM);

    // order: profiled launch (index 3) = lstm_persist_kernel
    init_gemm_kernel<<<16, 128>>>(context, W_ih, b_ih, W_ic, b_ic);
    xg_kernel<<<dim3(16, 16), 256>>>(tokens, emb, W_x, b_g);
    prep_kernel<<<144, 256>>>(W_out, b_out);
    lstm_persist_kernel<<<NCTA, 256, LSTM_SMEM>>>(W_h, tokens);
    logits_kernel<<<dim3(16, 250), 256>>>(out);
}

// round 16
// speedup vs baseline: 2.7893x; 1.0373x over previous
#include <cuda_runtime.h>
#include <cuda_bf16.h>
#include <cuda_fp16.h>
#include <cstdint>
#include <mma.h>

using namespace nvcuda;

#define VOCAB  32000
#define EMBED  512
#define HIDDEN 512
#define CTXD   2048
#define BB     32
#define SS     64
#define MTOT   (BB * SS)      // 2048
#define GATES  (4 * HIDDEN)   // 2048
#define NCTA   128
#define HSTEP  (HIDDEN * BB)  // 16384 halfs = 32KB per step

// ---------------- scratch (device globals; no allocation allowed) ----------------
__device__ float  g_xg[MTOT * GATES];                   // 16 MB
__device__ __half g_hs_h[MTOT * HIDDEN];                // 2 MB : [m][k] fp16 for logits
__device__ __align__(128) __half g_hseqh[SS * HSTEP];   // 2 MB : [t][k][b] fp16 (bulk-copy src)
__device__ __align__(128) __half g_h0Th[HSTEP];         // [k][b] fp16
__device__ float  g_c [BB * HIDDEN];
__device__ float  g_bias16[16 * VOCAB];                 // 2 MB : b_out replicated
__device__ __align__(128) __half g_wout_h[(size_t)VOCAB * HIDDEN];  // 33 MB fp16 W_out
__device__ unsigned g_bar[SS];

__device__ __forceinline__ unsigned smem_u32(const void* p) {
    return (unsigned)__cvta_generic_to_shared(p);
}
#define CPA16(d, s) asm volatile("cp.async.cg.shared.global [%0], [%1], 16;" :: "r"(d), "l"(s))

// ---------------- kernel prep: W_out->fp16, bias replicate, bar reset ----------------
__global__ __launch_bounds__(256) void prep_kernel(
    const float* __restrict__ Wout, const float* __restrict__ bout)
{
    const int tid = threadIdx.x;
    const int bx  = blockIdx.x;
    if (bx < 128) {
        const size_t base = (size_t)bx * 128000;
        for (int i = tid; i < 32000; i += 256) {
            const size_t off = base + (size_t)i * 4;
            float4 v = *(const float4*)(Wout + off);
            __half2* dst = (__half2*)(g_wout_h + off);
            dst[0] = __floats2half2_rn(v.x, v.y);
            dst[1] = __floats2half2_rn(v.z, v.w);
        }
    } else {
        const int r = bx - 128;
        for (int i = tid; i < VOCAB; i += 256)
            g_bias16[r * VOCAB + i] = bout[i];
        if (r == 0 && tid < SS) g_bar[tid] = 0;
    }
}

// ---------------- kernel 1: [h0|c0] = tanh(ctx @ [W_ih|W_ic] + bias)  (tf32 wmma) ----------------
__global__ __launch_bounds__(128) void init_gemm_kernel(
    const float* __restrict__ context,
    const float* __restrict__ W_ih, const float* __restrict__ b_ih,
    const float* __restrict__ W_ic, const float* __restrict__ b_ic)
{
    __shared__ float Asm[32 * 68];
    __shared__ float Bsm[64 * 68];

    const int tid = threadIdx.x;
    const int wid = tid >> 5;
    const int lane = tid & 31;
    const int n0 = blockIdx.x * 64;
    const bool which = (n0 >= 512);
    const int ncol = n0 & 511;
    const float* W  = which ? W_ic : W_ih;
    const float* bv = which ? b_ic : b_ih;

    wmma::fragment<wmma::accumulator, 16, 16, 8, float> acc0, acc1;
    wmma::fill_fragment(acc0, 0.f);
    wmma::fill_fragment(acc1, 0.f);

    for (int kc = 0; kc < 32; kc++) {
        const int k0 = kc * 64;
        {
            const int row = tid >> 2;
            const int cb  = (tid & 3) * 16;
            const float* src = context + (size_t)row * CTXD + k0 + cb;
            float* dst = Asm + row * 68 + cb;
#pragma unroll
            for (int i = 0; i < 4; i++) {
                float4 v = *(const float4*)(src + i * 4);
                dst[i * 4 + 0] = wmma::__float_to_tf32(v.x);
                dst[i * 4 + 1] = wmma::__float_to_tf32(v.y);
                dst[i * 4 + 2] = wmma::__float_to_tf32(v.z);
                dst[i * 4 + 3] = wmma::__float_to_tf32(v.w);
            }
        }
        {
            const int r  = tid >> 1;
            const int c0 = (tid & 1) * 4;
            const float* src = W + (size_t)(k0 + r) * HIDDEN + ncol + c0;
            float* dst = Bsm + r * 68 + c0;
#pragma unroll
            for (int i = 0; i < 8; i++) {
                float4 v = *(const float4*)(src + i * 8);
                dst[i * 8 + 0] = wmma::__float_to_tf32(v.x);
                dst[i * 8 + 1] = wmma::__float_to_tf32(v.y);
                dst[i * 8 + 2] = wmma::__float_to_tf32(v.z);
                dst[i * 8 + 3] = wmma::__float_to_tf32(v.w);
            }
        }
        __syncthreads();
#pragma unroll
        for (int ks = 0; ks < 8; ks++) {
            wmma::fragment<wmma::matrix_a, 16, 16, 8, wmma::precision::tf32, wmma::row_major> a0, a1;
            wmma::fragment<wmma::matrix_b, 16, 16, 8, wmma::precision::tf32, wmma::row_major> bf;
            wmma::load_matrix_sync(a0, &Asm[ks * 8], 68);
            wmma::load_matrix_sync(a1, &Asm[16 * 68 + ks * 8], 68);
            wmma::load_matrix_sync(bf, &Bsm[(ks * 8) * 68 + wid * 16], 68);
            wmma::mma_sync(acc0, a0, bf, acc0);
            wmma::mma_sync(acc1, a1, bf, acc1);
        }
        __syncthreads();
    }

    float* stage = Asm + wid * 640;
    wmma::store_matrix_sync(stage, acc0, 20, wmma::mem_row_major);
    wmma::store_matrix_sync(stage + 16 * 20, acc1, 20, wmma::mem_row_major);
    __syncwarp();
#pragma unroll
    for (int p = 0; p < 16; p++) {
        const int e = p * 32 + lane;
        const int r = e >> 4, c = e & 15;     // r = batch
        const int j = ncol + wid * 16 + c;
        const float v = tanhf(stage[r * 20 + c] + bv[j]);
        if (which) g_c   [r * HIDDEN + j] = v;
        else       g_h0Th[j * BB + r]     = __float2half_rn(v);
    }
}

// ---------------- kernel 2: xg = gather(emb)@W_x + b  (tf32 wmma) ----------------
__global__ __launch_bounds__(256) void xg_kernel(
    const int*   __restrict__ tokens,
    const float* __restrict__ emb,
    const float* __restrict__ Wx,
    const float* __restrict__ bias)
{
    __shared__ float As[2][128 * 20];
    __shared__ float Bs[2][16 * 132];

    const int tid = threadIdx.x;
    const int wid = tid >> 5;
    const int lane = tid & 31;
    const int wm = wid >> 2;
    const int wn = wid & 3;
    const int m0 = blockIdx.y * 128, n0 = blockIdx.x * 128;

    const int arow = tid >> 1;
    const int acol = (tid & 1) * 8;
    const int tok  = tokens[m0 + arow];
    const float* aptr = emb + (size_t)tok * EMBED + acol;
    const int brow = tid >> 4;
    const int bcol = (tid & 15) * 4;
    const float* bptr = Wx + (size_t)brow * GATES + n0 + bcol;

    wmma::fragment<wmma::accumulator, 16, 16, 8, float> acc[4][2];
#pragma unroll
    for (int i = 0; i < 4; i++)
#pragma unroll
        for (int j = 0; j < 2; j++) wmma::fill_fragment(acc[i][j], 0.f);

    auto load_chunk = [&](int buf, int k0) {
        {
            float* dst = &As[buf][arow * 20 + acol];
            float4 v0 = *(const float4*)(aptr + k0);
            float4 v1 = *(const float4*)(aptr + k0 + 4);
            dst[0] = wmma::__float_to_tf32(v0.x); dst[1] = wmma::__float_to_tf32(v0.y);
            dst[2] = wmma::__float_to_tf32(v0.z); dst[3] = wmma::__float_to_tf32(v0.w);
            dst[4] = wmma::__float_to_tf32(v1.x); dst[5] = wmma::__float_to_tf32(v1.y);
            dst[6] = wmma::__float_to_tf32(v1.z); dst[7] = wmma::__float_to_tf32(v1.w);
        }
        {
            float* dst = &Bs[buf][brow * 132 + bcol];
#pragma unroll
            for (int i = 0; i < 2; i++) {
                float4 v = *(const float4*)(bptr + (size_t)k0 * GATES + i * 64);
                dst[i * 64 + 0] = wmma::__float_to_tf32(v.x);
                dst[i * 64 + 1] = wmma::__float_to_tf32(v.y);
                dst[i * 64 + 2] = wmma::__float_to_tf32(v.z);
                dst[i * 64 + 3] = wmma::__float_to_tf32(v.w);
            }
        }
    };

    load_chunk(0, 0);
    __syncthreads();

    int buf = 0;
    for (int kc = 0; kc < 32; kc++) {
        if (kc < 31) load_chunk(buf ^ 1, (kc + 1) * 16);
#pragma unroll
        for (int ks = 0; ks < 2; ks++) {
            wmma::fragment<wmma::matrix_a, 16, 16, 8, wmma::precision::tf32, wmma::row_major> af[4];
            wmma::fragment<wmma::matrix_b, 16, 16, 8, wmma::precision::tf32, wmma::row_major> bf[2];
#pragma unroll
            for (int i = 0; i < 4; i++)
                wmma::load_matrix_sync(af[i], &As[buf][(wm * 64 + i * 16) * 20 + ks * 8], 20);
#pragma unroll
            for (int j = 0; j < 2; j++)
                wmma::load_matrix_sync(bf[j], &Bs[buf][(ks * 8) * 132 + wn * 32 + j * 16], 132);
#pragma unroll
            for (int i = 0; i < 4; i++)
#pragma unroll
                for (int j = 0; j < 2; j++)
                    wmma::mma_sync(acc[i][j], af[i], bf[j], acc[i][j]);
        }
        __syncthreads();
        buf ^= 1;
    }

    float* stage = ((float*)As) + wid * 320;
#pragma unroll
    for (int i = 0; i < 4; i++) {
#pragma unroll
        for (int j = 0; j < 2; j++) {
            wmma::store_matrix_sync(stage, acc[i][j], 20, wmma::mem_row_major);
            __syncwarp();
#pragma unroll
            for (int p = 0; p < 8; p++) {
                const int e = p * 32 + lane;
                const int row = e >> 4, col = e & 15;
                const int gm = m0 + wm * 64 + i * 16 + row;
                const int gn = n0 + wn * 32 + j * 16 + col;
                g_xg[(size_t)gm * GATES + gn] = stage[row * 20 + col] + __ldg(&bias[gn]);
            }
            __syncwarp();
        }
    }
}

// ---------------- kernel 3: persistent LSTM, fp16 recurrence + bulk h-broadcast ----------------
// hsm [k][b] halfs (32KB, one 32KB UBLKCP/step), wsm [k][c] halfs,
// red [w][c*32+b] floats (col_major acc stores -> fused conflict-free reduce).
#define HS_BYTES   32768
#define WS_BYTES   16384
#define RED_BYTES  16384            // 8 * 512 floats
#define LSTM_SMEM  (HS_BYTES + WS_BYTES + RED_BYTES + 512 + MTOT * 4)

__global__ __launch_bounds__(256) void lstm_persist_kernel(
    const float* __restrict__ Wh,
    const int*   __restrict__ tokens)
{
    extern __shared__ char smraw[];
    __half* hsm = (__half*)smraw;                          // [k][b] 512x32
    __half* wsm = (__half*)(smraw + HS_BYTES);             // [k][c] 512x16
    float*  red = (float*)(smraw + HS_BYTES + WS_BYTES);   // [w][c*32+b] 8x512
    float*  csm = (float*)(smraw + HS_BYTES + WS_BYTES + RED_BYTES);  // [128]
    int*    tsm = (int*)(csm + 128);                       // [2048]
    __shared__ alignas(8) unsigned long long mbar_sto;

    const int tid  = threadIdx.x;
    const int wid  = tid >> 5;
    const int jbase = blockIdx.x * 4;

    unsigned hsm_addr = smem_u32(hsm);
    unsigned mbar_addr = smem_u32(&mbar_sto);

    // one-time: W_h slice (fp16), c0, tokens, mbarrier
    for (int idx = tid; idx < 512 * 16; idx += 256) {
        const int k = idx >> 4, c = idx & 15;
        wsm[idx] = __float2half_rn(
            Wh[(size_t)k * GATES + ((c >> 2) << 9) + jbase + (c & 3)]);
    }
    if (tid < 128) {
        const int b = tid & 31, jl = tid >> 5;
        csm[tid] = g_c[b * HIDDEN + jbase + jl];
    }
    for (int idx = tid; idx < MTOT; idx += 256) tsm[idx] = tokens[idx];
    if (tid == 0)
        asm volatile("mbarrier.init.shared.b64 [%0], 1;" :: "r"(mbar_addr) : "memory");
    __syncthreads();

    // B fragments: warp wid owns k in [wid*64, wid*64+64) -> 4 frags of k16
    wmma::fragment<wmma::matrix_b, 16, 16, 16, __half, wmma::row_major> bk[4];
#pragma unroll
    for (int ks = 0; ks < 4; ks++)
        wmma::load_matrix_sync(bk[ks], &wsm[(wid * 64 + ks * 16) * 16], 16);
    __syncthreads();

    for (int t = 0; t < SS; t++) {
        // ---- one 32KB bulk copy of h_{t-1} ----
        if (tid == 0) {
            const __half* src = (t == 0) ? g_h0Th : (g_hseqh + (size_t)(t - 1) * HSTEP);
            asm volatile("mbarrier.arrive.expect_tx.shared.b64 _, [%0], %1;"
                         :: "r"(mbar_addr), "r"(32768u) : "memory");
            asm volatile("cp.async.bulk.shared::cta.global.mbarrier::complete_tx::bytes "
                         "[%0], [%1], %2, [%3];"
                         :: "r"(hsm_addr), "l"(src), "r"(32768u), "r"(mbar_addr) : "memory");
        }

        // ---- prefetch xg (overlaps copy) ----
        float x0 = 0.f, x1 = 0.f, x2 = 0.f, x3 = 0.f;
        int b_f = 0, jl_f = 0, m_f = 0;
        if (tid < 128) {
            b_f = tid & 31; jl_f = tid >> 5;
            m_f = (b_f << 6) + t;
            const size_t xb = (size_t)m_f * GATES + jbase + jl_f;
            x0 = g_xg[xb];
            x1 = g_xg[xb + 512];
            x2 = g_xg[xb + 1024];
            x3 = g_xg[xb + 1536];
        }

        // ---- wait for copy (phase parity = t&1) ----
        {
            const unsigned parity = (unsigned)(t & 1);
            unsigned done;
            do {
                asm volatile(
                    "{ .reg .pred p;\n\t"
                    "mbarrier.try_wait.parity.acquire.cta.shared::cta.b64 p, [%1], %2, 0x989680;\n\t"
                    "selp.b32 %0, 1, 0, p; }"
                    : "=r"(done) : "r"(mbar_addr), "r"(parity) : "memory");
            } while (!done);
        }

        // ---- fp16 HMMA: z-partials over this warp's 64-wide k slice ----
        wmma::fragment<wmma::accumulator, 16, 16, 16, float> acc0, acc1;
        wmma::fill_fragment(acc0, 0.f);
        wmma::fill_fragment(acc1, 0.f);
#pragma unroll
        for (int ks = 0; ks < 4; ks++) {
            const int k0 = wid * 64 + ks * 16;
            wmma::fragment<wmma::matrix_a, 16, 16, 16, __half, wmma::col_major> a0, a1;
            wmma::load_matrix_sync(a0, &hsm[k0 * BB],      BB);   // batches 0..15
            wmma::load_matrix_sync(a1, &hsm[k0 * BB + 16], BB);   // batches 16..31
            wmma::mma_sync(acc0, a0, bk[ks], acc0);
            wmma::mma_sync(acc1, a1, bk[ks], acc1);
        }
        // col_major store: red[w*512 + c*32 + b]
        wmma::store_matrix_sync(&red[wid * 512],      acc0, 32, wmma::mem_col_major);
        wmma::store_matrix_sync(&red[wid * 512 + 16], acc1, 32, wmma::mem_col_major);
        __syncthreads();

        // ---- fused reduce + finalize (conflict-free: b fastest) ----
        if (tid < 128) {
            const int b = b_f, jl = jl_f, m = m_f;
            const int j = jbase + jl;
            float zs[4] = {x0, x1, x2, x3};
#pragma unroll
            for (int g = 0; g < 4; g++) {
                const float* rp = red + (g * 4 + jl) * 32 + b;
                float s = 0.f;
#pragma unroll
                for (int w = 0; w < 8; w++) s += rp[w * 512];
                zs[g] += s;
            }
            const float c_old = csm[tid];
            const float si = 1.f / (1.f + expf(-zs[0]));
            const float sf = 1.f / (1.f + expf(-zs[1]));
            const float so = 1.f / (1.f + expf(-zs[3]));
            const float cn = sf * c_old + si * tanhf(zs[2]);
            const float hn = so * tanhf(cn);
            const bool msk = (tsm[m] != 0);
            const float hprev = __half2float(hsm[j * BB + b]);
            const float ho = msk ? hn : hprev;
            const float co = msk ? cn : c_old;
            csm[tid] = co;
            const __half hoh = __float2half_rn(ho);
            g_hs_h [(size_t)m * HIDDEN + j]       = hoh;   // [m][k] for logits
            g_hseqh[(size_t)t * HSTEP + j * BB + b] = hoh; // [t][k][b] for recurrence
        }

        // ---- grid barrier (tight spin, no sleep) ----
        if (t < SS - 1) {
            __threadfence();
            __syncthreads();
            if (tid == 0) {
                atomicAdd(&g_bar[t], 1u);
                while (((volatile unsigned*)g_bar)[t] < (unsigned)NCTA) { }
                __threadfence();
            }
            __syncthreads();
        }
    }
}

// ---------------- kernel 4: logits = hs @ W_out + b_out  (fp16 wmma, 3-stage cp.async) ----------------
#define LG_ALD 40
#define LG_BLD 136
#define LG_ABYTES (128 * LG_ALD * 2)   // 10240
#define LG_BBYTES (32 * LG_BLD * 2)    // 8704
#define LG_STAGE  (LG_ABYTES + LG_BBYTES)
#define LOGITS_SMEM (3 * LG_STAGE)     // 56832

__global__ __launch_bounds__(256) void logits_kernel(float* __restrict__ out)
{
    extern __shared__ char lsraw[];

    const int tid = threadIdx.x;
    const int wid = tid >> 5;
    const int wm = wid & 3;
    const int wn = wid >> 2;
    const int m0 = blockIdx.x * 128;
    const int n0 = blockIdx.y * 128;

    wmma::fragment<wmma::accumulator, 16, 16, 16, float> acc[2][4];
#pragma unroll
    for (int i = 0; i < 2; i++)
#pragma unroll
        for (int j = 0; j < 4; j++)
            wmma::load_matrix_sync(acc[i][j], g_bias16 + n0 + wn * 64 + j * 16,
                                   VOCAB, wmma::mem_row_major);

    const int arow = tid >> 1;
    const int acb  = (tid & 1) * 16;
    const __half* aptr = g_hs_h + (size_t)(m0 + arow) * HIDDEN + acb;
    const int brow = tid >> 3;
    const int bcb  = (tid & 7) * 16;
    const __half* bptr = g_wout_h + (size_t)brow * VOCAB + n0 + bcb;

    unsigned da[3], db[3];
#pragma unroll
    for (int s = 0; s < 3; s++) {
        da[s] = smem_u32(lsraw + s * LG_STAGE) + (arow * LG_ALD + acb) * 2;
        db[s] = smem_u32(lsraw + s * LG_STAGE + LG_ABYTES) + (brow * LG_BLD + bcb) * 2;
    }

    auto issue = [&](int s, int k0) {
        const __half* sa = aptr + k0;
        CPA16(da[s],      sa);
        CPA16(da[s] + 16, sa + 8);
        const __half* sb = bptr + (size_t)k0 * VOCAB;
        CPA16(db[s],      sb);
        CPA16(db[s] + 16, sb + 8);
        asm volatile("cp.async.commit_group;");
    };

    issue(0, 0);
    issue(1, 32);

    int s = 0;
#pragma unroll 1
    for (int kc = 0; kc < 16; kc++) {
        if (kc < 14) asm volatile("cp.async.wait_group 1;" ::: "memory");
        else         asm volatile("cp.async.wait_group 0;" ::: "memory");
        __syncthreads();
        if (kc < 14) issue((kc + 2) % 3, (kc + 2) * 32);

        const __half* As_s = (const __half*)(lsraw + s * LG_STAGE);
        const __half* Bs_s = (const __half*)(lsraw + s * LG_STAGE + LG_ABYTES);
#pragma unroll
        for (int ks = 0; ks < 2; ks++) {
            wmma::fragment<wmma::matrix_a, 16, 16, 16, __half, wmma::row_major> af[2];
            wmma::fragment<wmma::matrix_b, 16, 16, 16, __half, wmma::row_major> bf[4];
#pragma unroll
            for (int i = 0; i < 2; i++)
                wmma::load_matrix_sync(af[i], As_s + (wm * 32 + i * 16) * LG_ALD + ks * 16, LG_ALD);
#pragma unroll
            for (int j = 0; j < 4; j++)
                wmma::load_matrix_sync(bf[j], Bs_s + (ks * 16) * LG_BLD + wn * 64 + j * 16, LG_BLD);
#pragma unroll
            for (int i = 0; i < 2; i++)
#pragma unroll
                for (int j = 0; j < 4; j++)
                    wmma::mma_sync(acc[i][j], af[i], bf[j], acc[i][j]);
        }
        s = (s + 1) % 3;
    }

#pragma unroll
    for (int i = 0; i < 2; i++) {
#pragma unroll
        for (int j = 0; j < 4; j++) {
            const int gm = m0 + wm * 32 + i * 16;
            const int gn = n0 + wn * 64 + j * 16;
            wmma::store_matrix_sync(out + (size_t)gm * VOCAB + gn, acc[i][j],
                                    VOCAB, wmma::mem_row_major);
        }
    }
}

// ---------------- launch ----------------
extern "C" void kernel_launch(void* const* d_in, const int* in_sizes, int n_in,
                              void* d_out, int out_size)
{
    const int*   tokens  = (const int*)  d_in[0];
    const float* context = (const float*)d_in[1];
    const float* emb     = (const float*)d_in[2];
    const float* W_ih    = (const float*)d_in[3];
    const float* b_ih    = (const float*)d_in[4];
    const float* W_ic    = (const float*)d_in[5];
    const float* b_ic    = (const float*)d_in[6];
    const float* W_x     = (const float*)d_in[7];
    const float* W_h     = (const float*)d_in[8];
    const float* b_g     = (const float*)d_in[9];
    const float* W_out   = (const float*)d_in[10];
    const float* b_out   = (const float*)d_in[11];
    float* out = (float*)d_out;

    cudaFuncSetAttribute(lstm_persist_kernel,
                         cudaFuncAttributeMaxDynamicSharedMemorySize, LSTM_SMEM);
    cudaFuncSetAttribute(logits_kernel,
                         cudaFuncAttributeMaxDynamicSharedMemorySize, LOGITS_SMEM);

    // order: profiled launch (index 3) = lstm_persist_kernel
    init_gemm_kernel<<<16, 128>>>(context, W_ih, b_ih, W_ic, b_ic);
    xg_kernel<<<dim3(16, 16), 256>>>(tokens, emb, W_x, b_g);
    prep_kernel<<<144, 256>>>(W_out, b_out);
    lstm_persist_kernel<<<NCTA, 256, LSTM_SMEM>>>(W_h, tokens);
    logits_kernel<<<dim3(16, 250), 256, LOGITS_SMEM>>>(out);
}